// round 13
// baseline (speedup 1.0000x reference)
#include <cuda_runtime.h>
#include <cuda_fp16.h>
#include <cstdint>

// ---------------- problem constants ----------------
#define NSUP 25
#define NQ 400
#define SEQF 8
#define DIM 2048
#define DOUT 1024
#define TN 56
#define NWAY 5
#define SHOT 5
#define SACT 280            // shot*Tn real supports per class
#define SPACK 1408          // 5*280 packed + 8 pad = 11 x 128 tiles
#define NT3 (SPACK/128)     // 11 N-tiles in gemm3
#define QROWS 22400         // 400*56
#define QPAD 22528          // 176 x 128
#define MFR 3200            // query frames
#define MPAD 3584           // frame-row padding in g_Ah
#define CMPAD 2560          // compact gemm1 M (20 x 128)
#define NMB 20              // gemm1 m-blocks

// ticket layout
#define G1T 480             // 20 mb x 8 nb x 3 j
#define ASMT 427            // 25 sup + spad + qpad + 400 queries
#define G3T 1936            // 176 x 11
#define TICKETS (G1T + ASMT + G3T)
#define NCTA 296            // 2 x 148 SMs (guaranteed resident at 2/SM)

// ---------------- MMA smem layout (128x128 CTA, K-chunk 64, 3 stages) ----------------
#define TILE_BYTES 16384
#define STAGE_BYTES (2*TILE_BYTES)
#define SMEM_BYTES (3*STAGE_BYTES)         // 96 KB dynamic
#define SWZ(o) ((o) ^ (((o) >> 3) & 0x70))

__constant__ unsigned char TUP[TN][3] = {
  {0,1,2},{0,1,3},{0,1,4},{0,1,5},{0,1,6},{0,1,7},
  {0,2,3},{0,2,4},{0,2,5},{0,2,6},{0,2,7},
  {0,3,4},{0,3,5},{0,3,6},{0,3,7},
  {0,4,5},{0,4,6},{0,4,7},
  {0,5,6},{0,5,7},{0,6,7},
  {1,2,3},{1,2,4},{1,2,5},{1,2,6},{1,2,7},
  {1,3,4},{1,3,5},{1,3,6},{1,3,7},
  {1,4,5},{1,4,6},{1,4,7},
  {1,5,6},{1,5,7},{1,6,7},
  {2,3,4},{2,3,5},{2,3,6},{2,3,7},
  {2,4,5},{2,4,6},{2,4,7},
  {2,5,6},{2,5,7},{2,6,7},
  {3,4,5},{3,4,6},{3,4,7},
  {3,5,6},{3,5,7},{3,6,7},
  {4,5,6},{4,5,7},{4,6,7},
  {5,6,7}
};
__constant__ unsigned char CLS_E[NWAY][3] = {
  {0, 2, 4}, {5, 6, 8}, {9, 10, 12}, {13, 14, 16}, {17, 18, 20}
};

// ---------------- scratch ----------------
__device__ __align__(256) __half g_Ah[(size_t)MPAD*DIM];
__device__ __align__(256) __half g_Wh[(size_t)3*DOUT*DIM];
__device__ __align__(256) __half g_P[(size_t)MPAD*3*DOUT];
__device__ __align__(256) __half g_QE[(size_t)QPAD*DOUT];
__device__ __align__(256) float  g_q2[QPAD];
__device__ __align__(256) __half g_SE[(size_t)SPACK*DOUT];
__device__ __align__(256) float  g_s2[SPACK];
__device__ __align__(256) float  g_tmin[2*NT3][QPAD];
__device__ int g_sloc[NSUP];

// sync state (zero-init; reset by finalize for replays)
__device__ unsigned g_ticket;
__device__ unsigned g_mblk[NMB];          // gemm1 m-block completion (target 24)
__device__ unsigned g_vdone[NQ + 1];      // per-query-video flag, [NQ] = q-pad
__device__ unsigned g_sdone;              // supports + s-pad (target 26)

// ---------------- helpers ----------------
__device__ __forceinline__ uint32_t smem_u32(const void* p) {
    uint32_t a;
    asm("{ .reg .u64 t; cvta.to.shared.u64 t, %1; cvt.u32.u64 %0, t; }" : "=r"(a) : "l"(p));
    return a;
}
__device__ __forceinline__ void cp16(uint32_t s, const void* g) {
    asm volatile("cp.async.cg.shared.global [%0], [%1], 16;" :: "r"(s), "l"(g) : "memory");
}
#define LDSM4(r, addr) \
    asm volatile("ldmatrix.sync.aligned.m8n8.x4.shared.b16 {%0,%1,%2,%3}, [%4];" \
        : "=r"((r)[0]), "=r"((r)[1]), "=r"((r)[2]), "=r"((r)[3]) : "r"(addr))
#define MMA_F16(c, a, b0, b1) \
    asm volatile("mma.sync.aligned.m16n8k16.row.col.f32.f16.f16.f32 " \
        "{%0,%1,%2,%3}, {%4,%5,%6,%7}, {%8,%9}, {%0,%1,%2,%3};" \
        : "+f"((c)[0]), "+f"((c)[1]), "+f"((c)[2]), "+f"((c)[3]) \
        : "r"((a)[0]), "r"((a)[1]), "r"((a)[2]), "r"((a)[3]), "r"(b0), "r"(b1))

__device__ __forceinline__ void spin_ge(const unsigned* p, unsigned tgt) {
    while (*(volatile const unsigned*)p < tgt) __nanosleep(64);
}
__device__ __forceinline__ void mark_add(unsigned* p) {
    __threadfence();
    __syncthreads();
    if (threadIdx.x == 0) atomicAdd(p, 1u);
}

// ---------------- mainloop pieces: 256 thr, warps 2(M)x4(N), 64x32 tiles ----------
__device__ __forceinline__ void load_tile(uint32_t sbase, const __half* g,
                                          int stride, int chunk, int tid) {
    const __half* gp = g + (size_t)chunk * 64;
    #pragma unroll
    for (int i = 0; i < 4; i++) {
        int idx = i * 256 + tid;
        int row = idx >> 3, seg = idx & 7;
        cp16(sbase + SWZ(row * 128 + seg * 16), gp + (size_t)row * stride + seg * 8);
    }
}
__device__ __forceinline__ void load_tile_a(uint32_t sbase, int j, int mBase,
                                            int chunk, int tid) {
    const __half* gp = g_Ah + (size_t)chunk * 64;
    #pragma unroll
    for (int i = 0; i < 4; i++) {
        int idx = i * 256 + tid;
        int row = idx >> 3, seg = idx & 7;
        int cr = mBase + row;
        int orig = (cr / 6) * 8 + cr % 6 + j;
        cp16(sbase + SWZ(row * 128 + seg * 16), gp + (size_t)orig * DIM + seg * 8);
    }
}

struct LaneAddr { uint32_t aRowB, aXm, aK, bRowB, bXm, bK; };
__device__ __forceinline__ LaneAddr lane_addr(int tid) {
    const int l = tid & 31;
    const int wm = (tid >> 5) >> 2, wn = (tid >> 5) & 3;
    LaneAddr la;
    la.aRowB = (uint32_t)(wm * 64 + (l & 15)) * 128;
    la.aXm   = (uint32_t)(l & 7) << 4;
    la.aK    = ((l >> 4) & 1) * 16;
    la.bRowB = (uint32_t)(wn * 32 + (l & 7) + ((l >> 4) & 1) * 8) * 128;
    la.bXm   = (uint32_t)(l & 7) << 4;
    la.bK    = ((l >> 3) & 1) * 16;
    return la;
}
__device__ __forceinline__ void chunk_mma(uint32_t st, const LaneAddr& la,
                                          float acc[4][4][4]) {
    #pragma unroll
    for (int kk = 0; kk < 4; kk++) {
        uint32_t a[4][4], b[8];
        const uint32_t ao = ((kk * 32 + la.aK) ^ la.aXm) + la.aRowB;
        const uint32_t bo = ((kk * 32 + la.bK) ^ la.bXm) + la.bRowB + TILE_BYTES;
        #pragma unroll
        for (int mi = 0; mi < 4; mi++) LDSM4(a[mi], st + ao + mi * 2048);
        LDSM4(b + 0, st + bo);
        LDSM4(b + 4, st + bo + 2048);
        #pragma unroll
        for (int mi = 0; mi < 4; mi++)
            #pragma unroll
            for (int ni = 0; ni < 4; ni++)
                MMA_F16(acc[mi][ni], a[mi], b[ni * 2], b[ni * 2 + 1]);
    }
}

// ---------------- conversion / pack helpers ----------------
__device__ __forceinline__ uint2 pack_half4(float4 r) {
    __half h0 = __float2half_rn(r.x), h1 = __float2half_rn(r.y),
           h2 = __float2half_rn(r.z), h3 = __float2half_rn(r.w);
    uint2 p;
    p.x = (uint32_t)__half_as_ushort(h0) | ((uint32_t)__half_as_ushort(h1) << 16);
    p.y = (uint32_t)__half_as_ushort(h2) | ((uint32_t)__half_as_ushort(h3) << 16);
    return p;
}
__device__ __forceinline__ float sumsq_half4(uint2 p) {
    float f0 = __half2float(__ushort_as_half((unsigned short)(p.x & 0xffff)));
    float f1 = __half2float(__ushort_as_half((unsigned short)(p.x >> 16)));
    float f2 = __half2float(__ushort_as_half((unsigned short)(p.y & 0xffff)));
    float f3 = __half2float(__ushort_as_half((unsigned short)(p.y >> 16)));
    return f0 * f0 + f1 * f1 + f2 * f2 + f3 * f3;
}

#define NQ4 (MFR * DIM / 4)
#define NS4 ((MPAD - MFR) * DIM / 4)
#define NW4 (3 * DOUT * DIM / 4)

__global__ __launch_bounds__(256) void convAll(const float* __restrict__ q,
                                               const float* __restrict__ s,
                                               const float* __restrict__ W,
                                               const int* __restrict__ raw)
{
    if (blockIdx.x == 0 && threadIdx.x == 0) {
        bool is64 = true;
        for (int i = 1; i < NSUP; i += 2) if (raw[i] != 0) { is64 = false; break; }
        if (is64) for (int i = 0; i < NSUP; i += 2) if (raw[i] < 0 || raw[i] >= NWAY) { is64 = false; break; }
        int cnt[NWAY];
        #pragma unroll
        for (int c = 0; c < NWAY; ++c) cnt[c] = 0;
        for (int i = 0; i < NSUP; ++i) {
            int lab = is64 ? raw[2 * i] : raw[i];
            if (lab >= 0 && lab < NWAY && cnt[lab] < SHOT) {
                g_sloc[i] = lab * SHOT + cnt[lab];
                cnt[lab]++;
            }
        }
    }
    int i = blockIdx.x * 256 + threadIdx.x;
    if (i < NQ4) {
        *(uint2*)(g_Ah + (size_t)i * 4) = pack_half4(((const float4*)q)[i]);
    } else if (i < NQ4 + NS4) {
        i -= NQ4;
        uint2 p = make_uint2(0, 0);
        if (i < NSUP * SEQF * DIM / 4) p = pack_half4(((const float4*)s)[i]);
        *(uint2*)(g_Ah + (size_t)MFR * DIM + (size_t)i * 4) = p;
    } else if (i < NQ4 + NS4 + NW4) {
        i -= NQ4 + NS4;
        size_t e = (size_t)i * 4;
        int k = (int)(e & (DIM - 1));
        size_t r = e >> 11;
        int n = (int)(r & (DOUT - 1));
        int j = (int)(r >> 10);
        float4 x = *(const float4*)(W + (size_t)n * (3 * DIM) + (size_t)j * DIM + k);
        *(uint2*)(g_Wh + e) = pack_half4(x);
    }
}

// ---------------- phase bodies ----------------
__device__ void body_gemm1(char* smem, int nb, int j, int mb)
{
    const int nBase = nb * 128;
    const int mBase = mb * 128;
    const __half* B = g_Wh + ((size_t)j * DOUT + nBase) * DIM;
    float acc[4][4][4];
    #pragma unroll
    for (int a = 0; a < 4; a++)
        #pragma unroll
        for (int b = 0; b < 4; b++)
            #pragma unroll
            for (int c = 0; c < 4; c++) acc[a][b][c] = 0.f;

    const uint32_t sb = smem_u32(smem);
    const int tid = threadIdx.x;
    const LaneAddr la = lane_addr(tid);

    load_tile_a(sb, j, mBase, 0, tid);
    load_tile(sb + TILE_BYTES, B, DIM, 0, tid);
    asm volatile("cp.async.commit_group;" ::: "memory");
    load_tile_a(sb + STAGE_BYTES, j, mBase, 1, tid);
    load_tile(sb + STAGE_BYTES + TILE_BYTES, B, DIM, 1, tid);
    asm volatile("cp.async.commit_group;" ::: "memory");

    const int KC = DIM / 64;
    int stCur = 0, stNxt = 2;
    #pragma unroll 1
    for (int k = 0; k < KC; k++) {
        if (k + 2 < KC) { asm volatile("cp.async.wait_group 1;" ::: "memory"); }
        else            { asm volatile("cp.async.wait_group 0;" ::: "memory"); }
        __syncthreads();
        if (k + 2 < KC) {
            const uint32_t nx = sb + (uint32_t)stNxt * STAGE_BYTES;
            load_tile_a(nx, j, mBase, k + 2, tid);
            load_tile(nx + TILE_BYTES, B, DIM, k + 2, tid);
            asm volatile("cp.async.commit_group;" ::: "memory");
        }
        chunk_mma(sb + (uint32_t)stCur * STAGE_BYTES, la, acc);
        stCur = (stCur == 2) ? 0 : stCur + 1;
        stNxt = (stNxt == 2) ? 0 : stNxt + 1;
    }
    __syncthreads();

    const int l = tid & 31;
    const int wm = (tid >> 5) >> 2, wn = (tid >> 5) & 3;
    #pragma unroll
    for (int mi = 0; mi < 4; mi++) {
        const int c0 = mBase + wm * 64 + mi * 16 + (l >> 2);
        const int o0 = (c0 / 6) * 8 + c0 % 6 + j;
        const int c8 = c0 + 8;
        const int o8 = (c8 / 6) * 8 + c8 % 6 + j;
        #pragma unroll
        for (int ni = 0; ni < 4; ni++) {
            const int col = nBase + wn * 32 + ni * 8 + (l & 3) * 2;
            *(__half2*)(g_P + ((size_t)o0 * 3 + j) * DOUT + col) =
                __floats2half2_rn(acc[mi][ni][0], acc[mi][ni][1]);
            *(__half2*)(g_P + ((size_t)o8 * 3 + j) * DOUT + col) =
                __floats2half2_rn(acc[mi][ni][2], acc[mi][ni][3]);
        }
    }
    mark_add(&g_mblk[mb]);
}

__device__ void body_assemble(char* smemRaw, const float* __restrict__ bias,
                              const __half* __restrict__ srcP,
                              __half* __restrict__ dstE, float* __restrict__ dstN)
{
    __half* sP = (__half*)smemRaw;
    float* ws = (float*)(smemRaw + 24 * 1024 * 2);
    const int tid = threadIdx.x;
    {
        const uint2* s = (const uint2*)srcP;
        uint2* d = (uint2*)sP;
        #pragma unroll
        for (int i = 0; i < 24; i++) d[i * 256 + tid] = s[i * 256 + tid];
    }
    __syncthreads();
    const int o = tid * 4;
    const float4 vb = *(const float4*)(bias + o);
    const int l = tid & 31, wid = tid >> 5;
    #pragma unroll 4
    for (int t = 0; t < TN; t++) {
        const int f0 = TUP[t][0], f1 = TUP[t][1], f2 = TUP[t][2];
        uint2 pa = *(const uint2*)(sP + (f0 * 3 + 0) * DOUT + o);
        uint2 pb = *(const uint2*)(sP + (f1 * 3 + 1) * DOUT + o);
        uint2 pc = *(const uint2*)(sP + (f2 * 3 + 2) * DOUT + o);
        float2 a0 = __half22float2(*(__half2*)&pa.x), a1 = __half22float2(*(__half2*)&pa.y);
        float2 b0 = __half22float2(*(__half2*)&pb.x), b1 = __half22float2(*(__half2*)&pb.y);
        float2 c0 = __half22float2(*(__half2*)&pc.x), c1 = __half22float2(*(__half2*)&pc.y);
        float4 r;
        r.x = fmaxf(a0.x + b0.x + c0.x + vb.x, 0.f);
        r.y = fmaxf(a0.y + b0.y + c0.y + vb.y, 0.f);
        r.z = fmaxf(a1.x + b1.x + c1.x + vb.z, 0.f);
        r.w = fmaxf(a1.y + b1.y + c1.y + vb.w, 0.f);
        uint2 p = pack_half4(r);
        *(uint2*)(dstE + (size_t)t * DOUT + o) = p;
        float ss = sumsq_half4(p);
        #pragma unroll
        for (int s = 16; s > 0; s >>= 1) ss += __shfl_xor_sync(0xffffffffu, ss, s);
        if (l == 0) ws[t * 8 + wid] = ss;
    }
    __syncthreads();
    if (tid < TN) {
        float s = 0.f;
        #pragma unroll
        for (int i = 0; i < 8; i++) s += ws[tid * 8 + i];
        dstN[tid] = s;
    }
}

__device__ void body_gemm3(char* smem, int nt, int mt,
                           float s2s[128], float rowmin[128][4][2])
{
    const int nBase = nt * 128;
    const int mBase = mt * 128;
    const int tid = threadIdx.x, l = tid & 31;
    const int wm = (tid >> 5) >> 2, wn = (tid >> 5) & 3;

    if (tid < 128) s2s[tid] = g_s2[nBase + tid];

    const __half* A = g_QE + (size_t)mBase * DOUT;
    const __half* B = g_SE + (size_t)nBase * DOUT;
    float acc[4][4][4];
    #pragma unroll
    for (int a = 0; a < 4; a++)
        #pragma unroll
        for (int b = 0; b < 4; b++)
            #pragma unroll
            for (int d = 0; d < 4; d++) acc[a][b][d] = 0.f;

    const uint32_t sb = smem_u32(smem);
    const LaneAddr la = lane_addr(tid);

    load_tile(sb, A, DOUT, 0, tid);
    load_tile(sb + TILE_BYTES, B, DOUT, 0, tid);
    asm volatile("cp.async.commit_group;" ::: "memory");
    load_tile(sb + STAGE_BYTES, A, DOUT, 1, tid);
    load_tile(sb + STAGE_BYTES + TILE_BYTES, B, DOUT, 1, tid);
    asm volatile("cp.async.commit_group;" ::: "memory");

    const int KC = DOUT / 64;
    int stCur = 0, stNxt = 2;
    #pragma unroll 1
    for (int k = 0; k < KC; k++) {
        if (k + 2 < KC) { asm volatile("cp.async.wait_group 1;" ::: "memory"); }
        else            { asm volatile("cp.async.wait_group 0;" ::: "memory"); }
        __syncthreads();
        if (k + 2 < KC) {
            const uint32_t nx = sb + (uint32_t)stNxt * STAGE_BYTES;
            load_tile(nx, A, DOUT, k + 2, tid);
            load_tile(nx + TILE_BYTES, B, DOUT, k + 2, tid);
            asm volatile("cp.async.commit_group;" ::: "memory");
        }
        chunk_mma(sb + (uint32_t)stCur * STAGE_BYTES, la, acc);
        stCur = (stCur == 2) ? 0 : stCur + 1;
        stNxt = (stNxt == 2) ? 0 : stNxt + 1;
    }
    __syncthreads();

    const int cLo = min(nBase / SACT, NWAY - 1);
    float mnL0[4], mnL1[4], mnH0[4], mnH1[4];
    #pragma unroll
    for (int mi = 0; mi < 4; mi++) { mnL0[mi] = 3e38f; mnL1[mi] = 3e38f; mnH0[mi] = 3e38f; mnH1[mi] = 3e38f; }
    #pragma unroll
    for (int ni = 0; ni < 4; ni++) {
        const int col = wn * 32 + ni * 8 + (l & 3) * 2;
        const bool isHi = (min((nBase + col) / SACT, NWAY - 1) != cLo);
        const float sa = s2s[col], sbv = s2s[col + 1];
        #pragma unroll
        for (int mi = 0; mi < 4; mi++) {
            float v0 = fminf(fmaf(-2.f, acc[mi][ni][0], sa), fmaf(-2.f, acc[mi][ni][1], sbv));
            float v1 = fminf(fmaf(-2.f, acc[mi][ni][2], sa), fmaf(-2.f, acc[mi][ni][3], sbv));
            if (isHi) { mnH0[mi] = fminf(mnH0[mi], v0); mnH1[mi] = fminf(mnH1[mi], v1); }
            else      { mnL0[mi] = fminf(mnL0[mi], v0); mnL1[mi] = fminf(mnL1[mi], v1); }
        }
    }
    #pragma unroll
    for (int mi = 0; mi < 4; mi++) {
        #pragma unroll
        for (int s = 1; s <= 2; s <<= 1) {
            mnL0[mi] = fminf(mnL0[mi], __shfl_xor_sync(0xffffffffu, mnL0[mi], s));
            mnL1[mi] = fminf(mnL1[mi], __shfl_xor_sync(0xffffffffu, mnL1[mi], s));
            mnH0[mi] = fminf(mnH0[mi], __shfl_xor_sync(0xffffffffu, mnH0[mi], s));
            mnH1[mi] = fminf(mnH1[mi], __shfl_xor_sync(0xffffffffu, mnH1[mi], s));
        }
    }
    if ((l & 3) == 0) {
        #pragma unroll
        for (int mi = 0; mi < 4; mi++) {
            const int r0 = wm * 64 + mi * 16 + (l >> 2);
            rowmin[r0][wn][0] = mnL0[mi];      rowmin[r0][wn][1] = mnH0[mi];
            rowmin[r0 + 8][wn][0] = mnL1[mi];  rowmin[r0 + 8][wn][1] = mnH1[mi];
        }
    }
    __syncthreads();
    if (tid < 128) {
        float mL = fminf(fminf(rowmin[tid][0][0], rowmin[tid][1][0]),
                         fminf(rowmin[tid][2][0], rowmin[tid][3][0]));
        float mH = fminf(fminf(rowmin[tid][0][1], rowmin[tid][1][1]),
                         fminf(rowmin[tid][2][1], rowmin[tid][3][1]));
        g_tmin[2 * nt + 0][mBase + tid] = mL;
        g_tmin[2 * nt + 1][mBase + tid] = mH;
    }
}

// ---------------- megakernel: ticket-driven dataflow ----------------
__global__ __launch_bounds__(256, 2) void mega(const float* __restrict__ bias)
{
    extern __shared__ char smem[];
    __shared__ unsigned s_t;
    __shared__ float s2s[128];
    __shared__ float rowmin[128][4][2];
    const int tid = threadIdx.x;

    for (;;) {
        __syncthreads();                       // protect s_t reuse across iterations
        if (tid == 0) s_t = atomicAdd(&g_ticket, 1u);
        __syncthreads();
        const unsigned t = s_t;
        if (t >= TICKETS) return;

        if (t < G1T) {
            // m-block order: 19, 18, 0..17 (supports live in blocks 18/19)
            const int grp = t / 24, inner = t % 24;
            const int mb = (grp == 0) ? 19 : (grp == 1) ? 18 : (grp - 2);
            body_gemm1(smem, inner / 3, inner % 3, mb);
        } else if (t < G1T + ASMT) {
            const int a = t - G1T;
            if (a < NSUP) {
                const int n = a;
                const int r0 = 2400 + 6 * n;
                if (tid == 0) {
                    spin_ge(&g_mblk[r0 / 128], 24);
                    if ((r0 + 5) / 128 != r0 / 128) spin_ge(&g_mblk[(r0 + 5) / 128], 24);
                }
                __syncthreads();
                __threadfence();
                const int loc = g_sloc[n];
                const int base = (loc / SHOT) * SACT + (loc % SHOT) * TN;
                body_assemble(smem, bias,
                              g_P + (size_t)(MFR + n * SEQF) * 3 * DOUT,
                              g_SE + (size_t)base * DOUT, g_s2 + base);
                mark_add(&g_sdone);
            } else if (a == NSUP) {            // support pad cols
                for (int i = tid; i < (SPACK - NWAY * SACT) * DOUT / 4; i += 256)
                    *(uint2*)(g_SE + (size_t)NWAY * SACT * DOUT + (size_t)i * 4) = make_uint2(0, 0);
                if (tid < SPACK - NWAY * SACT) g_s2[NWAY * SACT + tid] = 1e30f;
                mark_add(&g_sdone);
            } else if (a == NSUP + 1) {        // query pad rows
                for (int i = tid; i < (QPAD - QROWS) * DOUT / 4; i += 256)
                    *(uint2*)(g_QE + (size_t)QROWS * DOUT + (size_t)i * 4) = make_uint2(0, 0);
                for (int i = tid; i < QPAD - QROWS; i += 256) g_q2[QROWS + i] = 0.f;
                __threadfence();
                __syncthreads();
                if (tid == 0) atomicExch(&g_vdone[NQ], 1u);
            } else {
                const int v = a - NSUP - 2;
                const int r0 = 6 * v;
                if (tid == 0) {
                    spin_ge(&g_mblk[r0 / 128], 24);
                    if ((r0 + 5) / 128 != r0 / 128) spin_ge(&g_mblk[(r0 + 5) / 128], 24);
                }
                __syncthreads();
                __threadfence();
                body_assemble(smem, bias,
                              g_P + (size_t)v * 24 * DOUT,
                              g_QE + (size_t)v * TN * DOUT, g_q2 + v * TN);
                __threadfence();
                __syncthreads();
                if (tid == 0) atomicExch(&g_vdone[v], 1u);
            }
        } else {
            const int g = t - G1T - ASMT;
            const int mt = g / NT3, nt = g % NT3;
            if (tid == 0) {
                spin_ge(&g_sdone, NSUP + 1);
                const int rlo = 128 * mt;
                const int vlo = rlo / 56, vhi = (rlo + 127) / 56;
                for (int v = vlo; v <= vhi && v < NQ; v++) spin_ge(&g_vdone[v], 1);
                if (vhi >= NQ) spin_ge(&g_vdone[NQ], 1);
            }
            __syncthreads();
            __threadfence();
            body_gemm3(smem, nt, mt, s2s, rowmin);
        }
    }
}

// ---------------- finalize (+ counter reset for graph replays) ----------------
__global__ void finalize(float* __restrict__ out)
{
    int idx = blockIdx.x * blockDim.x + threadIdx.x;
    if (idx == 0) { g_ticket = 0; g_sdone = 0; }
    if (idx < NMB) g_mblk[idx] = 0;
    if (idx < NQ + 1) g_vdone[idx] = 0;

    if (idx >= NQ * NWAY) return;
    int q = idx / NWAY, c = idx % NWAY;
    const int e0 = CLS_E[c][0], e1 = CLS_E[c][1], e2 = CLS_E[c][2];
    float s = 0.f;
    #pragma unroll 8
    for (int t = 0; t < TN; ++t) {
        const int row = q * TN + t;
        float m = fminf(fminf(g_tmin[e0][row], g_tmin[e1][row]), g_tmin[e2][row]);
        s += sqrtf(fmaxf(g_q2[row] + m, 0.f));
    }
    out[q * NWAY + c] = -s * (1.0f / (float)TN);
}

// ---------------- launch ----------------
extern "C" void kernel_launch(void* const* d_in, const int* in_sizes, int n_in,
                              void* d_out, int out_size)
{
    const float* support = (const float*)d_in[0];      // [25,8,2048]
    const int*   labraw  = (const int*)d_in[1];        // [25] int32/int64
    const float* queries = (const float*)d_in[2];      // [400,8,2048]
    const float* W       = (const float*)d_in[3];      // [1024,6144]
    const float* bias    = (const float*)d_in[4];      // [1024]
    float*       out     = (float*)d_out;              // [400,5]
    (void)in_sizes; (void)n_in; (void)out_size;

    cudaFuncSetAttribute(mega, cudaFuncAttributeMaxDynamicSharedMemorySize, SMEM_BYTES);

    convAll<<<(NQ4 + NS4 + NW4 + 255) / 256, 256>>>(queries, support, W, labraw);
    mega<<<NCTA, 256, SMEM_BYTES>>>(bias);
    finalize<<<(NQ * NWAY + 255) / 256, 256>>>(out);
}

// round 14
// speedup vs baseline: 1.2016x; 1.2016x over previous
#include <cuda_runtime.h>
#include <cuda_fp16.h>
#include <cstdint>

// ---------------- problem constants ----------------
#define NSUP 25
#define NQ 400
#define SEQF 8
#define DIM 2048
#define DOUT 1024
#define TN 56
#define NWAY 5
#define SHOT 5
#define SACT 280            // shot*Tn real supports per class
#define SPACK 1408          // 5*280 packed + 8 pad = 11 x 128 tiles
#define NT3 (SPACK/128)     // 11 N-tiles in gemm3
#define QROWS 22400         // 400*56 = 175 x 128 exactly (no padding needed)
#define NMT3 (QROWS/128)    // 175 M-tiles in gemm3
#define MFR 3200            // query frames
#define MPAD 3584           // frame-row padding in g_Ah
#define CMPAD 2560          // compact gemm1 M (20 x 128)

// ---------------- MMA smem layout (128x128 CTA, K-chunk 64, 3 stages) ----------------
#define TILE_BYTES 16384                   // 128 rows x 128B (64 fp16)
#define STAGE_BYTES (2*TILE_BYTES)         // A + B = 32 KB
#define SMEM_BYTES (3*STAGE_BYTES)         // 96 KB -> 2 CTAs/SM
#define SWZ(o) ((o) ^ (((o) >> 3) & 0x70))

// assembly smem: 24 vectors of 1024 fp16 + 56x8 fp32 reduce scratch
#define ASM_SMEM (24*1024*2 + TN*8*4)

// combinations(range(8),3), lexicographic
__constant__ unsigned char TUP[TN][3] = {
  {0,1,2},{0,1,3},{0,1,4},{0,1,5},{0,1,6},{0,1,7},
  {0,2,3},{0,2,4},{0,2,5},{0,2,6},{0,2,7},
  {0,3,4},{0,3,5},{0,3,6},{0,3,7},
  {0,4,5},{0,4,6},{0,4,7},
  {0,5,6},{0,5,7},{0,6,7},
  {1,2,3},{1,2,4},{1,2,5},{1,2,6},{1,2,7},
  {1,3,4},{1,3,5},{1,3,6},{1,3,7},
  {1,4,5},{1,4,6},{1,4,7},
  {1,5,6},{1,5,7},{1,6,7},
  {2,3,4},{2,3,5},{2,3,6},{2,3,7},
  {2,4,5},{2,4,6},{2,4,7},
  {2,5,6},{2,5,7},{2,6,7},
  {3,4,5},{3,4,6},{3,4,7},
  {3,5,6},{3,5,7},{3,6,7},
  {4,5,6},{4,5,7},{4,6,7},
  {5,6,7}
};

// class -> 3 (tile,half) entries; entry e: tile = e>>1, half = e&1
__constant__ unsigned char CLS_E[NWAY][3] = {
  {0, 2, 4}, {5, 6, 8}, {9, 10, 12}, {13, 14, 16}, {17, 18, 20}
};

// ---------------- scratch (__device__ globals) ----------------
__device__ __align__(256) __half g_Ah[(size_t)MPAD*DIM];          // frames fp16
__device__ __align__(256) __half g_Wh[(size_t)3*DOUT*DIM];        // W rearranged fp16
__device__ __align__(256) __half g_P[(size_t)MPAD*3*DOUT];        // partial embeddings fp16
__device__ __align__(256) __half g_QE[(size_t)QROWS*DOUT];        // query tuple emb fp16
__device__ __align__(256) float  g_q2[QROWS];
__device__ __align__(256) __half g_SE[(size_t)SPACK*DOUT];        // packed support emb
__device__ __align__(256) float  g_s2[SPACK];
__device__ __align__(256) float  g_tmin[2*NT3][QROWS];            // per-(tile,half) row mins
__device__ int g_sloc[NSUP];                                      // support n -> c*SHOT+shotRank

// ---------------- helpers ----------------
__device__ __forceinline__ uint32_t smem_u32(const void* p) {
    uint32_t a;
    asm("{ .reg .u64 t; cvta.to.shared.u64 t, %1; cvt.u32.u64 %0, t; }" : "=r"(a) : "l"(p));
    return a;
}
__device__ __forceinline__ void cp16(uint32_t s, const void* g) {
    asm volatile("cp.async.cg.shared.global [%0], [%1], 16;" :: "r"(s), "l"(g) : "memory");
}
#define LDSM4(r, addr) \
    asm volatile("ldmatrix.sync.aligned.m8n8.x4.shared.b16 {%0,%1,%2,%3}, [%4];" \
        : "=r"((r)[0]), "=r"((r)[1]), "=r"((r)[2]), "=r"((r)[3]) : "r"(addr))
#define MMA_F16(c, a, b0, b1) \
    asm volatile("mma.sync.aligned.m16n8k16.row.col.f32.f16.f16.f32 " \
        "{%0,%1,%2,%3}, {%4,%5,%6,%7}, {%8,%9}, {%0,%1,%2,%3};" \
        : "+f"((c)[0]), "+f"((c)[1]), "+f"((c)[2]), "+f"((c)[3]) \
        : "r"((a)[0]), "r"((a)[1]), "r"((a)[2]), "r"((a)[3]), "r"(b0), "r"(b1))

// ---------------- mainloop pieces: 256 thr, warps 2(M)x4(N), 64x32 tiles ----------
__device__ __forceinline__ void load_tile(uint32_t sbase, const __half* g,
                                          int stride, int chunk, int tid) {
    const __half* gp = g + (size_t)chunk * 64;
    #pragma unroll
    for (int i = 0; i < 4; i++) {
        int idx = i * 256 + tid;
        int row = idx >> 3, seg = idx & 7;
        cp16(sbase + SWZ(row * 128 + seg * 16), gp + (size_t)row * stride + seg * 8);
    }
}
// gemm1 A loader: compact row c -> source frame row (c/6)*8 + c%6 + j
__device__ __forceinline__ void load_tile_a(uint32_t sbase, int j, int mBase,
                                            int chunk, int tid) {
    const __half* gp = g_Ah + (size_t)chunk * 64;
    #pragma unroll
    for (int i = 0; i < 4; i++) {
        int idx = i * 256 + tid;
        int row = idx >> 3, seg = idx & 7;
        int cr = mBase + row;
        int orig = (cr / 6) * 8 + cr % 6 + j;
        cp16(sbase + SWZ(row * 128 + seg * 16), gp + (size_t)orig * DIM + seg * 8);
    }
}

struct LaneAddr {
    uint32_t aRowB, aXm, aK, bRowB, bXm, bK;
};
__device__ __forceinline__ LaneAddr lane_addr(int tid) {
    const int l = tid & 31;
    const int wm = (tid >> 5) >> 2, wn = (tid >> 5) & 3;
    LaneAddr la;
    la.aRowB = (uint32_t)(wm * 64 + (l & 15)) * 128;
    la.aXm   = (uint32_t)(l & 7) << 4;
    la.aK    = ((l >> 4) & 1) * 16;
    la.bRowB = (uint32_t)(wn * 32 + (l & 7) + ((l >> 4) & 1) * 8) * 128;
    la.bXm   = (uint32_t)(l & 7) << 4;
    la.bK    = ((l >> 3) & 1) * 16;
    return la;
}

__device__ __forceinline__ void chunk_mma(uint32_t st, const LaneAddr& la,
                                          float acc[4][4][4]) {
    #pragma unroll
    for (int kk = 0; kk < 4; kk++) {
        uint32_t a[4][4], b[8];
        const uint32_t ao = ((kk * 32 + la.aK) ^ la.aXm) + la.aRowB;
        const uint32_t bo = ((kk * 32 + la.bK) ^ la.bXm) + la.bRowB + TILE_BYTES;
        #pragma unroll
        for (int mi = 0; mi < 4; mi++) LDSM4(a[mi], st + ao + mi * 2048);
        LDSM4(b + 0, st + bo);
        LDSM4(b + 4, st + bo + 2048);
        #pragma unroll
        for (int mi = 0; mi < 4; mi++)
            #pragma unroll
            for (int ni = 0; ni < 4; ni++)
                MMA_F16(acc[mi][ni], a[mi], b[ni * 2], b[ni * 2 + 1]);
    }
}

// ---------------- merged conversion kernel (+ label decode in block 0) ----------------
__device__ __forceinline__ uint2 pack_half4(float4 r) {
    __half h0 = __float2half_rn(r.x), h1 = __float2half_rn(r.y),
           h2 = __float2half_rn(r.z), h3 = __float2half_rn(r.w);
    uint2 p;
    p.x = (uint32_t)__half_as_ushort(h0) | ((uint32_t)__half_as_ushort(h1) << 16);
    p.y = (uint32_t)__half_as_ushort(h2) | ((uint32_t)__half_as_ushort(h3) << 16);
    return p;
}
__device__ __forceinline__ float sumsq_half4(uint2 p) {
    float f0 = __half2float(__ushort_as_half((unsigned short)(p.x & 0xffff)));
    float f1 = __half2float(__ushort_as_half((unsigned short)(p.x >> 16)));
    float f2 = __half2float(__ushort_as_half((unsigned short)(p.y & 0xffff)));
    float f3 = __half2float(__ushort_as_half((unsigned short)(p.y >> 16)));
    return f0 * f0 + f1 * f1 + f2 * f2 + f3 * f3;
}

#define NQ4 (MFR * DIM / 4)                 // query quads
#define NS4 ((MPAD - MFR) * DIM / 4)        // support + pad quads
#define NW4 (3 * DOUT * DIM / 4)            // W quads

__global__ __launch_bounds__(256) void convAll(const float* __restrict__ q,
                                               const float* __restrict__ s,
                                               const float* __restrict__ W,
                                               const int* __restrict__ raw)
{
    if (blockIdx.x == 0 && threadIdx.x == 0) {
        bool is64 = true;
        for (int i = 1; i < NSUP; i += 2) if (raw[i] != 0) { is64 = false; break; }
        if (is64) for (int i = 0; i < NSUP; i += 2) if (raw[i] < 0 || raw[i] >= NWAY) { is64 = false; break; }
        int cnt[NWAY];
        #pragma unroll
        for (int c = 0; c < NWAY; ++c) cnt[c] = 0;
        for (int i = 0; i < NSUP; ++i) {
            int lab = is64 ? raw[2 * i] : raw[i];
            if (lab >= 0 && lab < NWAY && cnt[lab] < SHOT) {
                g_sloc[i] = lab * SHOT + cnt[lab];
                cnt[lab]++;
            }
        }
    }
    int i = blockIdx.x * 256 + threadIdx.x;
    if (i < NQ4) {
        *(uint2*)(g_Ah + (size_t)i * 4) = pack_half4(((const float4*)q)[i]);
    } else if (i < NQ4 + NS4) {
        i -= NQ4;
        uint2 p = make_uint2(0, 0);
        if (i < NSUP * SEQF * DIM / 4) p = pack_half4(((const float4*)s)[i]);
        *(uint2*)(g_Ah + (size_t)MFR * DIM + (size_t)i * 4) = p;
    } else if (i < NQ4 + NS4 + NW4) {
        i -= NQ4 + NS4;
        size_t e = (size_t)i * 4;
        int k = (int)(e & (DIM - 1));
        size_t r = e >> 11;
        int n = (int)(r & (DOUT - 1));
        int j = (int)(r >> 10);
        float4 x = *(const float4*)(W + (size_t)n * (3 * DIM) + (size_t)j * DIM + k);
        *(uint2*)(g_Wh + e) = pack_half4(x);
    }
}

// ---------------- stage 1: partial-embedding GEMM (compact M, fp16 output) --------
__global__ __launch_bounds__(256, 2) void gemm1()
{
    extern __shared__ char smem[];
    const int nBase = blockIdx.x * 128;
    const int j     = blockIdx.y;
    const int mBase = blockIdx.z * 128;          // compact row base
    const __half* B = g_Wh + ((size_t)j * DOUT + nBase) * DIM;

    float acc[4][4][4];
    #pragma unroll
    for (int a = 0; a < 4; a++)
        #pragma unroll
        for (int b = 0; b < 4; b++)
            #pragma unroll
            for (int c = 0; c < 4; c++) acc[a][b][c] = 0.f;

    const uint32_t sb = smem_u32(smem);
    const int tid = threadIdx.x;
    const LaneAddr la = lane_addr(tid);

    load_tile_a(sb, j, mBase, 0, tid);
    load_tile(sb + TILE_BYTES, B, DIM, 0, tid);
    asm volatile("cp.async.commit_group;" ::: "memory");
    load_tile_a(sb + STAGE_BYTES, j, mBase, 1, tid);
    load_tile(sb + STAGE_BYTES + TILE_BYTES, B, DIM, 1, tid);
    asm volatile("cp.async.commit_group;" ::: "memory");

    const int KC = DIM / 64;
    int stCur = 0, stNxt = 2;
    #pragma unroll 1
    for (int k = 0; k < KC; k++) {
        if (k + 2 < KC) { asm volatile("cp.async.wait_group 1;" ::: "memory"); }
        else            { asm volatile("cp.async.wait_group 0;" ::: "memory"); }
        __syncthreads();
        if (k + 2 < KC) {
            const uint32_t nx = sb + (uint32_t)stNxt * STAGE_BYTES;
            load_tile_a(nx, j, mBase, k + 2, tid);
            load_tile(nx + TILE_BYTES, B, DIM, k + 2, tid);
            asm volatile("cp.async.commit_group;" ::: "memory");
        }
        chunk_mma(sb + (uint32_t)stCur * STAGE_BYTES, la, acc);
        stCur = (stCur == 2) ? 0 : stCur + 1;
        stNxt = (stNxt == 2) ? 0 : stNxt + 1;
    }
    __syncthreads();

    const int l = tid & 31;
    const int wm = (tid >> 5) >> 2, wn = (tid >> 5) & 3;
    #pragma unroll
    for (int mi = 0; mi < 4; mi++) {
        const int c0 = mBase + wm * 64 + mi * 16 + (l >> 2);
        const int o0 = (c0 / 6) * 8 + c0 % 6 + j;
        const int c8 = c0 + 8;
        const int o8 = (c8 / 6) * 8 + c8 % 6 + j;
        #pragma unroll
        for (int ni = 0; ni < 4; ni++) {
            const int col = nBase + wn * 32 + ni * 8 + (l & 3) * 2;
            *(__half2*)(g_P + ((size_t)o0 * 3 + j) * DOUT + col) =
                __floats2half2_rn(acc[mi][ni][0], acc[mi][ni][1]);
            *(__half2*)(g_P + ((size_t)o8 * 3 + j) * DOUT + col) =
                __floats2half2_rn(acc[mi][ni][2], acc[mi][ni][3]);
        }
    }
}

// ---------------- stage 2: fused per-video assembly (fp16 staging) ----------------
__device__ __forceinline__ void assemble_video(
    const __half* __restrict__ srcP,    // 24 rows x 1024 fp16 (contiguous)
    __half* __restrict__ dstE,          // first of 56 output rows
    float* __restrict__ dstN,           // 56 norms
    const float* __restrict__ bias,
    char* smemRaw)
{
    __half* sP = (__half*)smemRaw;                       // 24*1024 fp16
    float* ws = (float*)(smemRaw + 24 * 1024 * 2);       // TN*8 floats
    const int tid = threadIdx.x;
    {
        const uint2* s = (const uint2*)srcP;
        uint2* d = (uint2*)sP;
        #pragma unroll
        for (int i = 0; i < 24; i++) d[i * 256 + tid] = s[i * 256 + tid];
    }
    __syncthreads();
    const int o = tid * 4;
    const float4 vb = *(const float4*)(bias + o);
    const int l = tid & 31, wid = tid >> 5;
    #pragma unroll 4
    for (int t = 0; t < TN; t++) {
        const int f0 = TUP[t][0], f1 = TUP[t][1], f2 = TUP[t][2];
        uint2 pa = *(const uint2*)(sP + (f0 * 3 + 0) * DOUT + o);
        uint2 pb = *(const uint2*)(sP + (f1 * 3 + 1) * DOUT + o);
        uint2 pc = *(const uint2*)(sP + (f2 * 3 + 2) * DOUT + o);
        float2 a0 = __half22float2(*(__half2*)&pa.x), a1 = __half22float2(*(__half2*)&pa.y);
        float2 b0 = __half22float2(*(__half2*)&pb.x), b1 = __half22float2(*(__half2*)&pb.y);
        float2 c0 = __half22float2(*(__half2*)&pc.x), c1 = __half22float2(*(__half2*)&pc.y);
        float4 r;
        r.x = fmaxf(a0.x + b0.x + c0.x + vb.x, 0.f);
        r.y = fmaxf(a0.y + b0.y + c0.y + vb.y, 0.f);
        r.z = fmaxf(a1.x + b1.x + c1.x + vb.z, 0.f);
        r.w = fmaxf(a1.y + b1.y + c1.y + vb.w, 0.f);
        uint2 p = pack_half4(r);
        *(uint2*)(dstE + (size_t)t * DOUT + o) = p;
        float ss = sumsq_half4(p);
        #pragma unroll
        for (int s = 16; s > 0; s >>= 1) ss += __shfl_xor_sync(0xffffffffu, ss, s);
        if (l == 0) ws[t * 8 + wid] = ss;
    }
    __syncthreads();
    if (tid < TN) {
        float s = 0.f;
        #pragma unroll
        for (int i = 0; i < 8; i++) s += ws[tid * 8 + i];
        dstN[tid] = s;
    }
}

// grid: [0..NQ) queries | [NQ..NQ+NSUP) supports | NQ+NSUP = s-pad
__global__ __launch_bounds__(256) void assembleQS(const float* __restrict__ bias)
{
    extern __shared__ char sRaw[];
    const int b = blockIdx.x;
    const int tid = threadIdx.x;
    if (b < NQ) {
        assemble_video(g_P + (size_t)b * 24 * DOUT,
                       g_QE + (size_t)b * TN * DOUT,
                       g_q2 + b * TN, bias, sRaw);
    } else if (b < NQ + NSUP) {
        const int n = b - NQ;
        const int loc = g_sloc[n];                    // c*SHOT + shotRank
        const int base = (loc / SHOT) * SACT + (loc % SHOT) * TN;
        assemble_video(g_P + (size_t)(MFR + n * SEQF) * 3 * DOUT,
                       g_SE + (size_t)base * DOUT,
                       g_s2 + base, bias, sRaw);
    } else {
        for (int i = tid; i < (SPACK - NWAY * SACT) * DOUT / 4; i += 256)
            *(uint2*)(g_SE + (size_t)NWAY * SACT * DOUT + (size_t)i * 4) = make_uint2(0, 0);
        if (tid < SPACK - NWAY * SACT) g_s2[NWAY * SACT + tid] = 1e30f;
    }
}

// ---------------- stage 3: fused distance GEMM + per-tile class-half min ----------------
__global__ __launch_bounds__(256, 2) void gemm3()
{
    extern __shared__ char smem[];
    __shared__ float s2s[128];
    __shared__ float rowmin[128][4][2];
    const int nt    = blockIdx.x;                // packed support tile
    const int nBase = nt * 128;
    const int mBase = blockIdx.y * 128;
    const int tid = threadIdx.x, l = tid & 31;
    const int wm = (tid >> 5) >> 2, wn = (tid >> 5) & 3;

    if (tid < 128) s2s[tid] = g_s2[nBase + tid];

    const __half* A = g_QE + (size_t)mBase * DOUT;
    const __half* B = g_SE + (size_t)nBase * DOUT;

    float acc[4][4][4];
    #pragma unroll
    for (int a = 0; a < 4; a++)
        #pragma unroll
        for (int b = 0; b < 4; b++)
            #pragma unroll
            for (int d = 0; d < 4; d++) acc[a][b][d] = 0.f;

    const uint32_t sb = smem_u32(smem);
    const LaneAddr la = lane_addr(tid);

    load_tile(sb, A, DOUT, 0, tid);
    load_tile(sb + TILE_BYTES, B, DOUT, 0, tid);
    asm volatile("cp.async.commit_group;" ::: "memory");
    load_tile(sb + STAGE_BYTES, A, DOUT, 1, tid);
    load_tile(sb + STAGE_BYTES + TILE_BYTES, B, DOUT, 1, tid);
    asm volatile("cp.async.commit_group;" ::: "memory");

    const int KC = DOUT / 64;
    int stCur = 0, stNxt = 2;
    #pragma unroll 1
    for (int k = 0; k < KC; k++) {
        if (k + 2 < KC) { asm volatile("cp.async.wait_group 1;" ::: "memory"); }
        else            { asm volatile("cp.async.wait_group 0;" ::: "memory"); }
        __syncthreads();
        if (k + 2 < KC) {
            const uint32_t nx = sb + (uint32_t)stNxt * STAGE_BYTES;
            load_tile(nx, A, DOUT, k + 2, tid);
            load_tile(nx + TILE_BYTES, B, DOUT, k + 2, tid);
            asm volatile("cp.async.commit_group;" ::: "memory");
        }
        chunk_mma(sb + (uint32_t)stCur * STAGE_BYTES, la, acc);
        stCur = (stCur == 2) ? 0 : stCur + 1;
        stNxt = (stNxt == 2) ? 0 : stNxt + 1;
    }
    __syncthreads();

    // segmented epilogue: tile spans at most 2 classes (boundary is even)
    const int cLo = min(nBase / SACT, NWAY - 1);
    float mnL0[4], mnL1[4], mnH0[4], mnH1[4];
    #pragma unroll
    for (int mi = 0; mi < 4; mi++) { mnL0[mi] = 3e38f; mnL1[mi] = 3e38f; mnH0[mi] = 3e38f; mnH1[mi] = 3e38f; }
    #pragma unroll
    for (int ni = 0; ni < 4; ni++) {
        const int col = wn * 32 + ni * 8 + (l & 3) * 2;
        const bool isHi = (min((nBase + col) / SACT, NWAY - 1) != cLo);
        const float sa = s2s[col], sbv = s2s[col + 1];
        #pragma unroll
        for (int mi = 0; mi < 4; mi++) {
            float v0 = fminf(fmaf(-2.f, acc[mi][ni][0], sa), fmaf(-2.f, acc[mi][ni][1], sbv));
            float v1 = fminf(fmaf(-2.f, acc[mi][ni][2], sa), fmaf(-2.f, acc[mi][ni][3], sbv));
            if (isHi) { mnH0[mi] = fminf(mnH0[mi], v0); mnH1[mi] = fminf(mnH1[mi], v1); }
            else      { mnL0[mi] = fminf(mnL0[mi], v0); mnL1[mi] = fminf(mnL1[mi], v1); }
        }
    }
    #pragma unroll
    for (int mi = 0; mi < 4; mi++) {
        #pragma unroll
        for (int s = 1; s <= 2; s <<= 1) {
            mnL0[mi] = fminf(mnL0[mi], __shfl_xor_sync(0xffffffffu, mnL0[mi], s));
            mnL1[mi] = fminf(mnL1[mi], __shfl_xor_sync(0xffffffffu, mnL1[mi], s));
            mnH0[mi] = fminf(mnH0[mi], __shfl_xor_sync(0xffffffffu, mnH0[mi], s));
            mnH1[mi] = fminf(mnH1[mi], __shfl_xor_sync(0xffffffffu, mnH1[mi], s));
        }
    }
    if ((l & 3) == 0) {
        #pragma unroll
        for (int mi = 0; mi < 4; mi++) {
            const int r0 = wm * 64 + mi * 16 + (l >> 2);
            rowmin[r0][wn][0] = mnL0[mi];      rowmin[r0][wn][1] = mnH0[mi];
            rowmin[r0 + 8][wn][0] = mnL1[mi];  rowmin[r0 + 8][wn][1] = mnH1[mi];
        }
    }
    __syncthreads();
    if (tid < 128) {
        float mL = fminf(fminf(rowmin[tid][0][0], rowmin[tid][1][0]),
                         fminf(rowmin[tid][2][0], rowmin[tid][3][0]));
        float mH = fminf(fminf(rowmin[tid][0][1], rowmin[tid][1][1]),
                         fminf(rowmin[tid][2][1], rowmin[tid][3][1]));
        g_tmin[2 * nt + 0][mBase + tid] = mL;
        g_tmin[2 * nt + 1][mBase + tid] = mH;
    }
}

// ---------------- stage 4: finalize ----------------
__global__ void finalize(float* __restrict__ out)
{
    int idx = blockIdx.x * blockDim.x + threadIdx.x;
    if (idx >= NQ * NWAY) return;
    int q = idx / NWAY, c = idx % NWAY;
    const int e0 = CLS_E[c][0], e1 = CLS_E[c][1], e2 = CLS_E[c][2];
    float s = 0.f;
    #pragma unroll 8
    for (int t = 0; t < TN; ++t) {
        const int row = q * TN + t;
        float m = fminf(fminf(g_tmin[e0][row], g_tmin[e1][row]), g_tmin[e2][row]);
        s += sqrtf(fmaxf(g_q2[row] + m, 0.f));
    }
    out[q * NWAY + c] = -s * (1.0f / (float)TN);
}

// ---------------- launch ----------------
extern "C" void kernel_launch(void* const* d_in, const int* in_sizes, int n_in,
                              void* d_out, int out_size)
{
    const float* support = (const float*)d_in[0];      // [25,8,2048]
    const int*   labraw  = (const int*)d_in[1];        // [25] int32/int64
    const float* queries = (const float*)d_in[2];      // [400,8,2048]
    const float* W       = (const float*)d_in[3];      // [1024,6144]
    const float* bias    = (const float*)d_in[4];      // [1024]
    float*       out     = (float*)d_out;              // [400,5]
    (void)in_sizes; (void)n_in; (void)out_size;

    cudaFuncSetAttribute(gemm1, cudaFuncAttributeMaxDynamicSharedMemorySize, SMEM_BYTES);
    cudaFuncSetAttribute(gemm3, cudaFuncAttributeMaxDynamicSharedMemorySize, SMEM_BYTES);
    cudaFuncSetAttribute(assembleQS, cudaFuncAttributeMaxDynamicSharedMemorySize, ASM_SMEM);

    convAll<<<(NQ4 + NS4 + NW4 + 255) / 256, 256>>>(queries, support, W, labraw);

    gemm1<<<dim3(DOUT / 128, 3, CMPAD / 128), 256, SMEM_BYTES>>>();

    assembleQS<<<NQ + NSUP + 1, 256, ASM_SMEM>>>(bias);

    gemm3<<<dim3(NT3, NMT3), 256, SMEM_BYTES>>>();

    finalize<<<(NQ * NWAY + 255) / 256, 256>>>(out);
}

// round 15
// speedup vs baseline: 1.2087x; 1.0060x over previous
#include <cuda_runtime.h>
#include <cuda_fp16.h>
#include <cstdint>

// ---------------- problem constants ----------------
#define NSUP 25
#define NQ 400
#define SEQF 8
#define DIM 2048
#define DOUT 1024
#define TN 56
#define NWAY 5
#define SHOT 5
#define SACT 280            // shot*Tn real supports per class
#define SPACK 1408          // 5*280 packed + 8 pad = 11 x 128 tiles
#define NT3 (SPACK/128)     // 11 N-tiles in gemm3
#define QROWS 22400         // 400*56 = 175 x 128 exactly
#define NMT3 (QROWS/128)    // 175 M-tiles in gemm3
#define MFR 3200            // query frames
#define MPAD 3584           // frame-row padding in g_Ah
#define CMPAD 2560          // compact gemm1 M (20 x 128)
#define NVID 425            // 400 query + 25 support videos

// ---------------- MMA smem layout (128x128 CTA, K-chunk 64, 3 stages) ----------------
#define TILE_BYTES 16384                   // 128 rows x 128B (64 fp16)
#define STAGE_BYTES (2*TILE_BYTES)         // A + B = 32 KB
#define SMEM_BYTES (3*STAGE_BYTES)         // 96 KB -> 2 CTAs/SM
#define SWZ(o) ((o) ^ (((o) >> 3) & 0x70))

// assembly smem: 18 vectors of 1024 fp16 + 56x8 fp32 reduce scratch
#define ASM_SMEM (18*1024*2 + TN*8*4)

// combinations(range(8),3), lexicographic
__constant__ unsigned char TUP[TN][3] = {
  {0,1,2},{0,1,3},{0,1,4},{0,1,5},{0,1,6},{0,1,7},
  {0,2,3},{0,2,4},{0,2,5},{0,2,6},{0,2,7},
  {0,3,4},{0,3,5},{0,3,6},{0,3,7},
  {0,4,5},{0,4,6},{0,4,7},
  {0,5,6},{0,5,7},{0,6,7},
  {1,2,3},{1,2,4},{1,2,5},{1,2,6},{1,2,7},
  {1,3,4},{1,3,5},{1,3,6},{1,3,7},
  {1,4,5},{1,4,6},{1,4,7},
  {1,5,6},{1,5,7},{1,6,7},
  {2,3,4},{2,3,5},{2,3,6},{2,3,7},
  {2,4,5},{2,4,6},{2,4,7},
  {2,5,6},{2,5,7},{2,6,7},
  {3,4,5},{3,4,6},{3,4,7},
  {3,5,6},{3,5,7},{3,6,7},
  {4,5,6},{4,5,7},{4,6,7},
  {5,6,7}
};

// class -> 3 (tile,half) entries; entry e: tile = e>>1, half = e&1
__constant__ unsigned char CLS_E[NWAY][3] = {
  {0, 2, 4}, {5, 6, 8}, {9, 10, 12}, {13, 14, 16}, {17, 18, 20}
};

// ---------------- scratch (__device__ globals) ----------------
__device__ __align__(256) __half g_Ah[(size_t)MPAD*DIM];          // frames fp16
__device__ __align__(256) __half g_Wh[(size_t)3*DOUT*DIM];        // W rearranged fp16
__device__ __align__(256) __half g_P[(size_t)NVID*18*DOUT + 1024];// compact partials fp16
__device__ __align__(256) __half g_QE[(size_t)QROWS*DOUT];        // query tuple emb fp16
__device__ __align__(256) float  g_q2[QROWS];
__device__ __align__(256) __half g_SE[(size_t)SPACK*DOUT];        // packed support emb
__device__ __align__(256) float  g_s2[SPACK];
__device__ __align__(256) float  g_tmin[2*NT3][QROWS];            // per-(tile,half) row mins
__device__ int g_sloc[NSUP];                                      // support n -> c*SHOT+shotRank

// ---------------- helpers ----------------
__device__ __forceinline__ uint32_t smem_u32(const void* p) {
    uint32_t a;
    asm("{ .reg .u64 t; cvta.to.shared.u64 t, %1; cvt.u32.u64 %0, t; }" : "=r"(a) : "l"(p));
    return a;
}
__device__ __forceinline__ void cp16(uint32_t s, const void* g) {
    asm volatile("cp.async.cg.shared.global [%0], [%1], 16;" :: "r"(s), "l"(g) : "memory");
}
#define LDSM4(r, addr) \
    asm volatile("ldmatrix.sync.aligned.m8n8.x4.shared.b16 {%0,%1,%2,%3}, [%4];" \
        : "=r"((r)[0]), "=r"((r)[1]), "=r"((r)[2]), "=r"((r)[3]) : "r"(addr))
#define MMA_F16(c, a, b0, b1) \
    asm volatile("mma.sync.aligned.m16n8k16.row.col.f32.f16.f16.f32 " \
        "{%0,%1,%2,%3}, {%4,%5,%6,%7}, {%8,%9}, {%0,%1,%2,%3};" \
        : "+f"((c)[0]), "+f"((c)[1]), "+f"((c)[2]), "+f"((c)[3]) \
        : "r"((a)[0]), "r"((a)[1]), "r"((a)[2]), "r"((a)[3]), "r"(b0), "r"(b1))

// ---------------- mainloop pieces: 256 thr, warps 2(M)x4(N), 64x32 tiles ----------
__device__ __forceinline__ void load_tile(uint32_t sbase, const __half* g,
                                          int stride, int chunk, int tid) {
    const __half* gp = g + (size_t)chunk * 64;
    #pragma unroll
    for (int i = 0; i < 4; i++) {
        int idx = i * 256 + tid;
        int row = idx >> 3, seg = idx & 7;
        cp16(sbase + SWZ(row * 128 + seg * 16), gp + (size_t)row * stride + seg * 8);
    }
}
// gemm1 A loader: compact row c -> source frame row (c/6)*8 + c%6 + j
__device__ __forceinline__ void load_tile_a(uint32_t sbase, int j, int mBase,
                                            int chunk, int tid) {
    const __half* gp = g_Ah + (size_t)chunk * 64;
    #pragma unroll
    for (int i = 0; i < 4; i++) {
        int idx = i * 256 + tid;
        int row = idx >> 3, seg = idx & 7;
        int cr = mBase + row;
        int orig = (cr / 6) * 8 + cr % 6 + j;
        cp16(sbase + SWZ(row * 128 + seg * 16), gp + (size_t)orig * DIM + seg * 8);
    }
}

struct LaneAddr {
    uint32_t aRowB, aXm, aK, bRowB, bXm, bK;
};
__device__ __forceinline__ LaneAddr lane_addr(int tid) {
    const int l = tid & 31;
    const int wm = (tid >> 5) >> 2, wn = (tid >> 5) & 3;
    LaneAddr la;
    la.aRowB = (uint32_t)(wm * 64 + (l & 15)) * 128;
    la.aXm   = (uint32_t)(l & 7) << 4;
    la.aK    = ((l >> 4) & 1) * 16;
    la.bRowB = (uint32_t)(wn * 32 + (l & 7) + ((l >> 4) & 1) * 8) * 128;
    la.bXm   = (uint32_t)(l & 7) << 4;
    la.bK    = ((l >> 3) & 1) * 16;
    return la;
}

__device__ __forceinline__ void chunk_mma(uint32_t st, const LaneAddr& la,
                                          float acc[4][4][4]) {
    #pragma unroll
    for (int kk = 0; kk < 4; kk++) {
        uint32_t a[4][4], b[8];
        const uint32_t ao = ((kk * 32 + la.aK) ^ la.aXm) + la.aRowB;
        const uint32_t bo = ((kk * 32 + la.bK) ^ la.bXm) + la.bRowB + TILE_BYTES;
        #pragma unroll
        for (int mi = 0; mi < 4; mi++) LDSM4(a[mi], st + ao + mi * 2048);
        LDSM4(b + 0, st + bo);
        LDSM4(b + 4, st + bo + 2048);
        #pragma unroll
        for (int mi = 0; mi < 4; mi++)
            #pragma unroll
            for (int ni = 0; ni < 4; ni++)
                MMA_F16(acc[mi][ni], a[mi], b[ni * 2], b[ni * 2 + 1]);
    }
}

// ---------------- merged conversion kernel (+ label decode + SE pad) ----------------
__device__ __forceinline__ uint2 pack_half4(float4 r) {
    __half h0 = __float2half_rn(r.x), h1 = __float2half_rn(r.y),
           h2 = __float2half_rn(r.z), h3 = __float2half_rn(r.w);
    uint2 p;
    p.x = (uint32_t)__half_as_ushort(h0) | ((uint32_t)__half_as_ushort(h1) << 16);
    p.y = (uint32_t)__half_as_ushort(h2) | ((uint32_t)__half_as_ushort(h3) << 16);
    return p;
}
__device__ __forceinline__ float sumsq_half4(uint2 p) {
    float f0 = __half2float(__ushort_as_half((unsigned short)(p.x & 0xffff)));
    float f1 = __half2float(__ushort_as_half((unsigned short)(p.x >> 16)));
    float f2 = __half2float(__ushort_as_half((unsigned short)(p.y & 0xffff)));
    float f3 = __half2float(__ushort_as_half((unsigned short)(p.y >> 16)));
    return f0 * f0 + f1 * f1 + f2 * f2 + f3 * f3;
}

#define NQ4 (MFR * DIM / 4)                 // query quads
#define NS4 ((MPAD - MFR) * DIM / 4)        // support + pad quads
#define NW4 (3 * DOUT * DIM / 4)            // W quads
#define NP4 ((SPACK - NWAY * SACT) * DOUT / 4)  // SE pad quads

__global__ __launch_bounds__(256) void convAll(const float* __restrict__ q,
                                               const float* __restrict__ s,
                                               const float* __restrict__ W,
                                               const int* __restrict__ raw)
{
    if (blockIdx.x == 0 && threadIdx.x == 0) {
        bool is64 = true;
        for (int i = 1; i < NSUP; i += 2) if (raw[i] != 0) { is64 = false; break; }
        if (is64) for (int i = 0; i < NSUP; i += 2) if (raw[i] < 0 || raw[i] >= NWAY) { is64 = false; break; }
        int cnt[NWAY];
        #pragma unroll
        for (int c = 0; c < NWAY; ++c) cnt[c] = 0;
        for (int i = 0; i < NSUP; ++i) {
            int lab = is64 ? raw[2 * i] : raw[i];
            if (lab >= 0 && lab < NWAY && cnt[lab] < SHOT) {
                g_sloc[i] = lab * SHOT + cnt[lab];
                cnt[lab]++;
            }
        }
    }
    if (blockIdx.x == 1 && threadIdx.x < SPACK - NWAY * SACT)
        g_s2[NWAY * SACT + threadIdx.x] = 1e30f;

    int i = blockIdx.x * 256 + threadIdx.x;
    if (i < NQ4) {
        *(uint2*)(g_Ah + (size_t)i * 4) = pack_half4(((const float4*)q)[i]);
    } else if (i < NQ4 + NS4) {
        i -= NQ4;
        uint2 p = make_uint2(0, 0);
        if (i < NSUP * SEQF * DIM / 4) p = pack_half4(((const float4*)s)[i]);
        *(uint2*)(g_Ah + (size_t)MFR * DIM + (size_t)i * 4) = p;
    } else if (i < NQ4 + NS4 + NW4) {
        i -= NQ4 + NS4;
        size_t e = (size_t)i * 4;
        int k = (int)(e & (DIM - 1));
        size_t r = e >> 11;
        int n = (int)(r & (DOUT - 1));
        int j = (int)(r >> 10);
        float4 x = *(const float4*)(W + (size_t)n * (3 * DIM) + (size_t)j * DIM + k);
        *(uint2*)(g_Wh + e) = pack_half4(x);
    } else if (i < NQ4 + NS4 + NW4 + NP4) {
        i -= NQ4 + NS4 + NW4;
        *(uint2*)(g_SE + (size_t)NWAY * SACT * DOUT + (size_t)i * 4) = make_uint2(0, 0);
    }
}

// ---------------- stage 1: partial-embedding GEMM (compact M, compact P) --------
__global__ __launch_bounds__(256, 2) void gemm1()
{
    extern __shared__ char smem[];
    const int nBase = blockIdx.x * 128;
    const int j     = blockIdx.y;
    const int mBase = blockIdx.z * 128;          // compact row base
    const __half* B = g_Wh + ((size_t)j * DOUT + nBase) * DIM;

    float acc[4][4][4];
    #pragma unroll
    for (int a = 0; a < 4; a++)
        #pragma unroll
        for (int b = 0; b < 4; b++)
            #pragma unroll
            for (int c = 0; c < 4; c++) acc[a][b][c] = 0.f;

    const uint32_t sb = smem_u32(smem);
    const int tid = threadIdx.x;
    const LaneAddr la = lane_addr(tid);

    load_tile_a(sb, j, mBase, 0, tid);
    load_tile(sb + TILE_BYTES, B, DIM, 0, tid);
    asm volatile("cp.async.commit_group;" ::: "memory");
    load_tile_a(sb + STAGE_BYTES, j, mBase, 1, tid);
    load_tile(sb + STAGE_BYTES + TILE_BYTES, B, DIM, 1, tid);
    asm volatile("cp.async.commit_group;" ::: "memory");

    const int KC = DIM / 64;
    int stCur = 0, stNxt = 2;
    #pragma unroll 1
    for (int k = 0; k < KC; k++) {
        if (k + 2 < KC) { asm volatile("cp.async.wait_group 1;" ::: "memory"); }
        else            { asm volatile("cp.async.wait_group 0;" ::: "memory"); }
        __syncthreads();
        if (k + 2 < KC) {
            const uint32_t nx = sb + (uint32_t)stNxt * STAGE_BYTES;
            load_tile_a(nx, j, mBase, k + 2, tid);
            load_tile(nx + TILE_BYTES, B, DIM, k + 2, tid);
            asm volatile("cp.async.commit_group;" ::: "memory");
        }
        chunk_mma(sb + (uint32_t)stCur * STAGE_BYTES, la, acc);
        stCur = (stCur == 2) ? 0 : stCur + 1;
        stNxt = (stNxt == 2) ? 0 : stNxt + 1;
    }
    __syncthreads();

    // compact P row for (video v, slice j, r) = v*18 + j*6 + r
    const int l = tid & 31;
    const int wm = (tid >> 5) >> 2, wn = (tid >> 5) & 3;
    #pragma unroll
    for (int mi = 0; mi < 4; mi++) {
        const int c0 = mBase + wm * 64 + mi * 16 + (l >> 2);
        const int o0 = (c0 / 6) * 18 + j * 6 + c0 % 6;
        const int c8 = c0 + 8;
        const int o8 = (c8 / 6) * 18 + j * 6 + c8 % 6;
        #pragma unroll
        for (int ni = 0; ni < 4; ni++) {
            const int col = nBase + wn * 32 + ni * 8 + (l & 3) * 2;
            *(__half2*)(g_P + (size_t)o0 * DOUT + col) =
                __floats2half2_rn(acc[mi][ni][0], acc[mi][ni][1]);
            *(__half2*)(g_P + (size_t)o8 * DOUT + col) =
                __floats2half2_rn(acc[mi][ni][2], acc[mi][ni][3]);
        }
    }
}

// ---------------- stage 2: fused per-video assembly (18-row compact staging) ------
__device__ __forceinline__ void assemble_video(
    const __half* __restrict__ srcP,    // 18 rows x 1024 fp16 (contiguous)
    __half* __restrict__ dstE,          // first of 56 output rows
    float* __restrict__ dstN,           // 56 norms
    const float* __restrict__ bias,
    char* smemRaw)
{
    __half* sP = (__half*)smemRaw;                       // 18*1024 fp16
    float* ws = (float*)(smemRaw + 18 * 1024 * 2);       // TN*8 floats
    const int tid = threadIdx.x;
    {
        const uint2* s = (const uint2*)srcP;
        uint2* d = (uint2*)sP;
        #pragma unroll
        for (int i = 0; i < 18; i++) d[i * 256 + tid] = s[i * 256 + tid];
    }
    __syncthreads();
    const int o = tid * 4;
    const float4 vb = *(const float4*)(bias + o);
    const int l = tid & 31, wid = tid >> 5;
    #pragma unroll 4
    for (int t = 0; t < TN; t++) {
        // slice j uses r = f_j - j within its 6-row band
        const int r0i = TUP[t][0];          // j=0: r = f0
        const int r1i = 6 + TUP[t][1] - 1;  // j=1: r = f1-1
        const int r2i = 12 + TUP[t][2] - 2; // j=2: r = f2-2
        uint2 pa = *(const uint2*)(sP + r0i * DOUT + o);
        uint2 pb = *(const uint2*)(sP + r1i * DOUT + o);
        uint2 pc = *(const uint2*)(sP + r2i * DOUT + o);
        float2 a0 = __half22float2(*(__half2*)&pa.x), a1 = __half22float2(*(__half2*)&pa.y);
        float2 b0 = __half22float2(*(__half2*)&pb.x), b1 = __half22float2(*(__half2*)&pb.y);
        float2 c0 = __half22float2(*(__half2*)&pc.x), c1 = __half22float2(*(__half2*)&pc.y);
        float4 r;
        r.x = fmaxf(a0.x + b0.x + c0.x + vb.x, 0.f);
        r.y = fmaxf(a0.y + b0.y + c0.y + vb.y, 0.f);
        r.z = fmaxf(a1.x + b1.x + c1.x + vb.z, 0.f);
        r.w = fmaxf(a1.y + b1.y + c1.y + vb.w, 0.f);
        uint2 p = pack_half4(r);
        *(uint2*)(dstE + (size_t)t * DOUT + o) = p;
        float ss = sumsq_half4(p);
        #pragma unroll
        for (int s = 16; s > 0; s >>= 1) ss += __shfl_xor_sync(0xffffffffu, ss, s);
        if (l == 0) ws[t * 8 + wid] = ss;
    }
    __syncthreads();
    if (tid < TN) {
        float s = 0.f;
        #pragma unroll
        for (int i = 0; i < 8; i++) s += ws[tid * 8 + i];
        dstN[tid] = s;
    }
}

// grid: [0..NQ) queries | [NQ..NQ+NSUP) supports
__global__ __launch_bounds__(256) void assembleQS(const float* __restrict__ bias)
{
    extern __shared__ char sRaw[];
    const int b = blockIdx.x;
    if (b < NQ) {
        assemble_video(g_P + (size_t)b * 18 * DOUT,
                       g_QE + (size_t)b * TN * DOUT,
                       g_q2 + b * TN, bias, sRaw);
    } else {
        const int n = b - NQ;
        const int loc = g_sloc[n];                    // c*SHOT + shotRank
        const int base = (loc / SHOT) * SACT + (loc % SHOT) * TN;
        assemble_video(g_P + (size_t)(NQ + n) * 18 * DOUT,
                       g_SE + (size_t)base * DOUT,
                       g_s2 + base, bias, sRaw);
    }
}

// ---------------- stage 3: fused distance GEMM + per-tile class-half min ----------------
__global__ __launch_bounds__(256, 2) void gemm3()
{
    extern __shared__ char smem[];
    __shared__ float s2s[128];
    __shared__ float rowmin[128][4][2];
    const int nt    = blockIdx.x;                // packed support tile
    const int nBase = nt * 128;
    const int mBase = blockIdx.y * 128;
    const int tid = threadIdx.x, l = tid & 31;
    const int wm = (tid >> 5) >> 2, wn = (tid >> 5) & 3;

    if (tid < 128) s2s[tid] = g_s2[nBase + tid];

    const __half* A = g_QE + (size_t)mBase * DOUT;
    const __half* B = g_SE + (size_t)nBase * DOUT;

    float acc[4][4][4];
    #pragma unroll
    for (int a = 0; a < 4; a++)
        #pragma unroll
        for (int b = 0; b < 4; b++)
            #pragma unroll
            for (int d = 0; d < 4; d++) acc[a][b][d] = 0.f;

    const uint32_t sb = smem_u32(smem);
    const LaneAddr la = lane_addr(tid);

    load_tile(sb, A, DOUT, 0, tid);
    load_tile(sb + TILE_BYTES, B, DOUT, 0, tid);
    asm volatile("cp.async.commit_group;" ::: "memory");
    load_tile(sb + STAGE_BYTES, A, DOUT, 1, tid);
    load_tile(sb + STAGE_BYTES + TILE_BYTES, B, DOUT, 1, tid);
    asm volatile("cp.async.commit_group;" ::: "memory");

    const int KC = DOUT / 64;
    int stCur = 0, stNxt = 2;
    #pragma unroll 1
    for (int k = 0; k < KC; k++) {
        if (k + 2 < KC) { asm volatile("cp.async.wait_group 1;" ::: "memory"); }
        else            { asm volatile("cp.async.wait_group 0;" ::: "memory"); }
        __syncthreads();
        if (k + 2 < KC) {
            const uint32_t nx = sb + (uint32_t)stNxt * STAGE_BYTES;
            load_tile(nx, A, DOUT, k + 2, tid);
            load_tile(nx + TILE_BYTES, B, DOUT, k + 2, tid);
            asm volatile("cp.async.commit_group;" ::: "memory");
        }
        chunk_mma(sb + (uint32_t)stCur * STAGE_BYTES, la, acc);
        stCur = (stCur == 2) ? 0 : stCur + 1;
        stNxt = (stNxt == 2) ? 0 : stNxt + 1;
    }
    __syncthreads();

    // segmented epilogue: tile spans at most 2 classes (boundary is even)
    const int cLo = min(nBase / SACT, NWAY - 1);
    float mnL0[4], mnL1[4], mnH0[4], mnH1[4];
    #pragma unroll
    for (int mi = 0; mi < 4; mi++) { mnL0[mi] = 3e38f; mnL1[mi] = 3e38f; mnH0[mi] = 3e38f; mnH1[mi] = 3e38f; }
    #pragma unroll
    for (int ni = 0; ni < 4; ni++) {
        const int col = wn * 32 + ni * 8 + (l & 3) * 2;
        const bool isHi = (min((nBase + col) / SACT, NWAY - 1) != cLo);
        const float sa = s2s[col], sbv = s2s[col + 1];
        #pragma unroll
        for (int mi = 0; mi < 4; mi++) {
            float v0 = fminf(fmaf(-2.f, acc[mi][ni][0], sa), fmaf(-2.f, acc[mi][ni][1], sbv));
            float v1 = fminf(fmaf(-2.f, acc[mi][ni][2], sa), fmaf(-2.f, acc[mi][ni][3], sbv));
            if (isHi) { mnH0[mi] = fminf(mnH0[mi], v0); mnH1[mi] = fminf(mnH1[mi], v1); }
            else      { mnL0[mi] = fminf(mnL0[mi], v0); mnL1[mi] = fminf(mnL1[mi], v1); }
        }
    }
    #pragma unroll
    for (int mi = 0; mi < 4; mi++) {
        #pragma unroll
        for (int s = 1; s <= 2; s <<= 1) {
            mnL0[mi] = fminf(mnL0[mi], __shfl_xor_sync(0xffffffffu, mnL0[mi], s));
            mnL1[mi] = fminf(mnL1[mi], __shfl_xor_sync(0xffffffffu, mnL1[mi], s));
            mnH0[mi] = fminf(mnH0[mi], __shfl_xor_sync(0xffffffffu, mnH0[mi], s));
            mnH1[mi] = fminf(mnH1[mi], __shfl_xor_sync(0xffffffffu, mnH1[mi], s));
        }
    }
    if ((l & 3) == 0) {
        #pragma unroll
        for (int mi = 0; mi < 4; mi++) {
            const int r0 = wm * 64 + mi * 16 + (l >> 2);
            rowmin[r0][wn][0] = mnL0[mi];      rowmin[r0][wn][1] = mnH0[mi];
            rowmin[r0 + 8][wn][0] = mnL1[mi];  rowmin[r0 + 8][wn][1] = mnH1[mi];
        }
    }
    __syncthreads();
    if (tid < 128) {
        float mL = fminf(fminf(rowmin[tid][0][0], rowmin[tid][1][0]),
                         fminf(rowmin[tid][2][0], rowmin[tid][3][0]));
        float mH = fminf(fminf(rowmin[tid][0][1], rowmin[tid][1][1]),
                         fminf(rowmin[tid][2][1], rowmin[tid][3][1]));
        g_tmin[2 * nt + 0][mBase + tid] = mL;
        g_tmin[2 * nt + 1][mBase + tid] = mH;
    }
}

// ---------------- stage 4: finalize ----------------
__global__ void finalize(float* __restrict__ out)
{
    int idx = blockIdx.x * blockDim.x + threadIdx.x;
    if (idx >= NQ * NWAY) return;
    int q = idx / NWAY, c = idx % NWAY;
    const int e0 = CLS_E[c][0], e1 = CLS_E[c][1], e2 = CLS_E[c][2];
    float s = 0.f;
    #pragma unroll 8
    for (int t = 0; t < TN; ++t) {
        const int row = q * TN + t;
        float m = fminf(fminf(g_tmin[e0][row], g_tmin[e1][row]), g_tmin[e2][row]);
        s += sqrtf(fmaxf(g_q2[row] + m, 0.f));
    }
    out[q * NWAY + c] = -s * (1.0f / (float)TN);
}

// ---------------- launch ----------------
extern "C" void kernel_launch(void* const* d_in, const int* in_sizes, int n_in,
                              void* d_out, int out_size)
{
    const float* support = (const float*)d_in[0];      // [25,8,2048]
    const int*   labraw  = (const int*)d_in[1];        // [25] int32/int64
    const float* queries = (const float*)d_in[2];      // [400,8,2048]
    const float* W       = (const float*)d_in[3];      // [1024,6144]
    const float* bias    = (const float*)d_in[4];      // [1024]
    float*       out     = (float*)d_out;              // [400,5]
    (void)in_sizes; (void)n_in; (void)out_size;

    cudaFuncSetAttribute(gemm1, cudaFuncAttributeMaxDynamicSharedMemorySize, SMEM_BYTES);
    cudaFuncSetAttribute(gemm3, cudaFuncAttributeMaxDynamicSharedMemorySize, SMEM_BYTES);
    cudaFuncSetAttribute(assembleQS, cudaFuncAttributeMaxDynamicSharedMemorySize, ASM_SMEM);

    convAll<<<(NQ4 + NS4 + NW4 + NP4 + 255) / 256, 256>>>(queries, support, W, labraw);

    gemm1<<<dim3(DOUT / 128, 3, CMPAD / 128), 256, SMEM_BYTES>>>();

    assembleQS<<<NQ + NSUP, 256, ASM_SMEM>>>(bias);

    gemm3<<<dim3(NT3, NMT3), 256, SMEM_BYTES>>>();

    finalize<<<(NQ * NWAY + 255) / 256, 256>>>(out);
}

// round 16
// speedup vs baseline: 1.2134x; 1.0039x over previous
#include <cuda_runtime.h>
#include <cuda_fp16.h>
#include <cstdint>

// ---------------- problem constants ----------------
#define NSUP 25
#define NQ 400
#define SEQF 8
#define DIM 2048
#define DOUT 1024
#define TN 56
#define NWAY 5
#define SHOT 5
#define SACT 280            // shot*Tn real supports per class
#define SPACK 1408          // 5*280 packed + 8 pad = 11 x 128 tiles
#define NT3 (SPACK/128)     // 11 N-tiles in gemm3
#define QROWS 22400         // 400*56 = 175 x 128 exactly
#define NMT3 (QROWS/128)    // 175 M-tiles in gemm3
#define CMROWS 2550         // compact gemm1 rows (425 videos x 6)
#define CMPAD 2560          // 20 x 128
#define NVID 425

// ---------------- MMA smem layout (128x128 CTA, K-chunk 64, 3 stages) ----------------
#define TILE_BYTES 16384                   // 128 rows x 128B (64 fp16)
#define STAGE_BYTES (2*TILE_BYTES)         // A + B = 32 KB
#define SMEM_BYTES (3*STAGE_BYTES)         // 96 KB -> 2 CTAs/SM

// assembly smem: 18 vectors of 1024 fp16 + 56x8 fp32 reduce scratch
#define ASM_SMEM (18*1024*2 + TN*8*4)

// combinations(range(8),3), lexicographic
__constant__ unsigned char TUP[TN][3] = {
  {0,1,2},{0,1,3},{0,1,4},{0,1,5},{0,1,6},{0,1,7},
  {0,2,3},{0,2,4},{0,2,5},{0,2,6},{0,2,7},
  {0,3,4},{0,3,5},{0,3,6},{0,3,7},
  {0,4,5},{0,4,6},{0,4,7},
  {0,5,6},{0,5,7},{0,6,7},
  {1,2,3},{1,2,4},{1,2,5},{1,2,6},{1,2,7},
  {1,3,4},{1,3,5},{1,3,6},{1,3,7},
  {1,4,5},{1,4,6},{1,4,7},
  {1,5,6},{1,5,7},{1,6,7},
  {2,3,4},{2,3,5},{2,3,6},{2,3,7},
  {2,4,5},{2,4,6},{2,4,7},
  {2,5,6},{2,5,7},{2,6,7},
  {3,4,5},{3,4,6},{3,4,7},
  {3,5,6},{3,5,7},{3,6,7},
  {4,5,6},{4,5,7},{4,6,7},
  {5,6,7}
};

// class -> 3 (tile,half) entries; entry e: tile = e>>1, half = e&1
__constant__ unsigned char CLS_E[NWAY][3] = {
  {0, 2, 4}, {5, 6, 8}, {9, 10, 12}, {13, 14, 16}, {17, 18, 20}
};

// ---------------- scratch: chunk-major pre-swizzled operand layouts ----------------
// plane(chunk) = [rows][64 halves], row pre-swizzled: off = byte ^ ((row&7)<<4)
__device__ __align__(256) __half g_Ac[(size_t)3*32*CMPAD*64];     // gemm1 A  31.5 MB
__device__ __align__(256) __half g_Wc[(size_t)3*32*DOUT*64];      // gemm1 B  12.6 MB
__device__ __align__(256) __half g_QEc[(size_t)16*QROWS*64];      // gemm3 A  45.9 MB
__device__ __align__(256) __half g_SEc[(size_t)16*SPACK*64];      // gemm3 B   2.9 MB
__device__ __align__(256) __half g_P[(size_t)NVID*18*DOUT];       // compact partials fp16
__device__ __align__(256) float  g_q2[QROWS];
__device__ __align__(256) float  g_s2[SPACK];
__device__ __align__(256) float  g_tmin[2*NT3][QROWS];
__device__ int g_sloc[NSUP];

// ---------------- helpers ----------------
__device__ __forceinline__ uint32_t smem_u32(const void* p) {
    uint32_t a;
    asm("{ .reg .u64 t; cvta.to.shared.u64 t, %1; cvt.u32.u64 %0, t; }" : "=r"(a) : "l"(p));
    return a;
}
#define LDSM4(r, addr) \
    asm volatile("ldmatrix.sync.aligned.m8n8.x4.shared.b16 {%0,%1,%2,%3}, [%4];" \
        : "=r"((r)[0]), "=r"((r)[1]), "=r"((r)[2]), "=r"((r)[3]) : "r"(addr))
#define MMA_F16(c, a, b0, b1) \
    asm volatile("mma.sync.aligned.m16n8k16.row.col.f32.f16.f16.f32 " \
        "{%0,%1,%2,%3}, {%4,%5,%6,%7}, {%8,%9}, {%0,%1,%2,%3};" \
        : "+f"((c)[0]), "+f"((c)[1]), "+f"((c)[2]), "+f"((c)[3]) \
        : "r"((a)[0]), "r"((a)[1]), "r"((a)[2]), "r"((a)[3]), "r"(b0), "r"(b1))

#define MB_INIT(a, c)  asm volatile("mbarrier.init.shared.b64 [%0], %1;" :: "r"(a), "r"((uint32_t)(c)) : "memory")
#define MB_EXPECT(a, b) asm volatile("mbarrier.arrive.expect_tx.shared.b64 _, [%0], %1;" :: "r"(a), "r"((uint32_t)(b)) : "memory")
#define BULK_G2S(dst, src, n, mb) \
    asm volatile("cp.async.bulk.shared::cta.global.mbarrier::complete_tx::bytes [%0], [%1], %2, [%3];" \
        :: "r"(dst), "l"(src), "r"((uint32_t)(n)), "r"(mb) : "memory")
#define MB_WAIT(mb, par) do { \
    uint32_t _mb = (mb); uint32_t _p = (par); uint32_t _d; \
    asm volatile("{\n\t.reg .pred p;\n\tmbarrier.try_wait.parity.acquire.cta.shared::cta.b64 p, [%1], %2;\n\tselp.b32 %0, 1, 0, p;\n\t}" \
        : "=r"(_d) : "r"(_mb), "r"(_p) : "memory"); \
    if (!_d) { \
        asm volatile("{\n\t.reg .pred P1;\n\tWL_%=:\n\tmbarrier.try_wait.parity.acquire.cta.shared::cta.b64 P1, [%0], %1, 0x989680;\n\t@P1 bra.uni WD_%=;\n\tbra.uni WL_%=;\n\tWD_%=:\n\t}" \
            :: "r"(_mb), "r"(_p) : "memory"); \
    } \
} while (0)

// ---------------- MMA core: 256 thr, warps 2(M)x4(N), 64x32 tiles -----------------
struct LaneAddr {
    uint32_t aRowB, aXm, aK, bRowB, bXm, bK;
};
__device__ __forceinline__ LaneAddr lane_addr(int tid) {
    const int l = tid & 31;
    const int wm = (tid >> 5) >> 2, wn = (tid >> 5) & 3;
    LaneAddr la;
    la.aRowB = (uint32_t)(wm * 64 + (l & 15)) * 128;
    la.aXm   = (uint32_t)(l & 7) << 4;
    la.aK    = ((l >> 4) & 1) * 16;
    la.bRowB = (uint32_t)(wn * 32 + (l & 7) + ((l >> 4) & 1) * 8) * 128;
    la.bXm   = (uint32_t)(l & 7) << 4;
    la.bK    = ((l >> 3) & 1) * 16;
    return la;
}
__device__ __forceinline__ void chunk_mma(uint32_t st, const LaneAddr& la,
                                          float acc[4][4][4]) {
    #pragma unroll
    for (int kk = 0; kk < 4; kk++) {
        uint32_t a[4][4], b[8];
        const uint32_t ao = ((kk * 32 + la.aK) ^ la.aXm) + la.aRowB;
        const uint32_t bo = ((kk * 32 + la.bK) ^ la.bXm) + la.bRowB + TILE_BYTES;
        #pragma unroll
        for (int mi = 0; mi < 4; mi++) LDSM4(a[mi], st + ao + mi * 2048);
        LDSM4(b + 0, st + bo);
        LDSM4(b + 4, st + bo + 2048);
        #pragma unroll
        for (int mi = 0; mi < 4; mi++)
            #pragma unroll
            for (int ni = 0; ni < 4; ni++)
                MMA_F16(acc[mi][ni], a[mi], b[ni * 2], b[ni * 2 + 1]);
    }
}

// bulk-fed mainloop: tiles are contiguous 16KB blocks in chunk-major planes
template<int KC>
__device__ __forceinline__ void mma_mainloop_bulk(
    const __half* Ap, int aRows, int aBase,
    const __half* Bp, int bRows, int bBase,
    char* smem, uint64_t* mbarS, float acc[4][4][4])
{
    const uint32_t sb = smem_u32(smem);
    const uint32_t mb = smem_u32(mbarS);
    const int tid = threadIdx.x;
    const LaneAddr la = lane_addr(tid);

    if (tid == 0) {
        #pragma unroll
        for (int s = 0; s < 3; s++) MB_INIT(mb + 8 * s, 1);
    }
    __syncthreads();
    if (tid == 0) {
        #pragma unroll
        for (int c = 0; c < 2; c++) {
            MB_EXPECT(mb + 8 * c, 2 * TILE_BYTES);
            BULK_G2S(sb + c * STAGE_BYTES,
                     Ap + ((size_t)c * aRows + aBase) * 64, TILE_BYTES, mb + 8 * c);
            BULK_G2S(sb + c * STAGE_BYTES + TILE_BYTES,
                     Bp + ((size_t)c * bRows + bBase) * 64, TILE_BYTES, mb + 8 * c);
        }
    }

    #pragma unroll 1
    for (int k = 0; k < KC; k++) {
        const int s = k % 3;
        const int par = (k / 3) & 1;
        MB_WAIT(mb + 8 * s, par);
        __syncthreads();                       // all warps done reading stage of k-1
        if (k + 2 < KC && tid == 0) {
            const int s2 = (k + 2) % 3;
            MB_EXPECT(mb + 8 * s2, 2 * TILE_BYTES);
            BULK_G2S(sb + s2 * STAGE_BYTES,
                     Ap + ((size_t)(k + 2) * aRows + aBase) * 64, TILE_BYTES, mb + 8 * s2);
            BULK_G2S(sb + s2 * STAGE_BYTES + TILE_BYTES,
                     Bp + ((size_t)(k + 2) * bRows + bBase) * 64, TILE_BYTES, mb + 8 * s2);
        }
        chunk_mma(sb + (uint32_t)s * STAGE_BYTES, la, acc);
    }
    __syncthreads();
}

// ---------------- pack helpers ----------------
__device__ __forceinline__ uint2 pack_half4(float4 r) {
    __half h0 = __float2half_rn(r.x), h1 = __float2half_rn(r.y),
           h2 = __float2half_rn(r.z), h3 = __float2half_rn(r.w);
    uint2 p;
    p.x = (uint32_t)__half_as_ushort(h0) | ((uint32_t)__half_as_ushort(h1) << 16);
    p.y = (uint32_t)__half_as_ushort(h2) | ((uint32_t)__half_as_ushort(h3) << 16);
    return p;
}
__device__ __forceinline__ float sumsq_half4(uint2 p) {
    float f0 = __half2float(__ushort_as_half((unsigned short)(p.x & 0xffff)));
    float f1 = __half2float(__ushort_as_half((unsigned short)(p.x >> 16)));
    float f2 = __half2float(__ushort_as_half((unsigned short)(p.y & 0xffff)));
    float f3 = __half2float(__ushort_as_half((unsigned short)(p.y >> 16)));
    return f0 * f0 + f1 * f1 + f2 * f2 + f3 * f3;
}

// ---------------- convAll: inputs -> pre-swizzled chunk-major fp16 ----------------
#define NQQ (NQ * SEQF * DIM / 4)           // query quads
#define NSQ (NSUP * SEQF * DIM / 4)         // support quads
#define NWQ (3 * DOUT * DIM / 4)            // W quads
#define NPQ (16 * (SPACK - NWAY * SACT) * 16) // SE pad quads (16 chunks x 8 rows x 16)

__global__ __launch_bounds__(256) void convAll(const float* __restrict__ q,
                                               const float* __restrict__ s,
                                               const float* __restrict__ W,
                                               const int* __restrict__ raw)
{
    if (blockIdx.x == 0 && threadIdx.x == 0) {
        bool is64 = true;
        for (int i = 1; i < NSUP; i += 2) if (raw[i] != 0) { is64 = false; break; }
        if (is64) for (int i = 0; i < NSUP; i += 2) if (raw[i] < 0 || raw[i] >= NWAY) { is64 = false; break; }
        int cnt[NWAY];
        #pragma unroll
        for (int c = 0; c < NWAY; ++c) cnt[c] = 0;
        for (int i = 0; i < NSUP; ++i) {
            int lab = is64 ? raw[2 * i] : raw[i];
            if (lab >= 0 && lab < NWAY && cnt[lab] < SHOT) {
                g_sloc[i] = lab * SHOT + cnt[lab];
                cnt[lab]++;
            }
        }
    }
    if (blockIdx.x == 1 && threadIdx.x < SPACK - NWAY * SACT)
        g_s2[NWAY * SACT + threadIdx.x] = 1e30f;

    int i = blockIdx.x * 256 + threadIdx.x;
    if (i < NQQ + NSQ) {
        // frame element -> g_Ac for each slice j using it
        float4 x; int v, f, k;
        if (i < NQQ) {
            x = ((const float4*)q)[i];
            size_t e = (size_t)i * 4;
            int frow = (int)(e >> 11); k = (int)(e & 2047);
            v = frow >> 3; f = frow & 7;
        } else {
            int ii = i - NQQ;
            x = ((const float4*)s)[ii];
            size_t e = (size_t)ii * 4;
            int frow = (int)(e >> 11); k = (int)(e & 2047);
            v = NQ + (frow >> 3); f = frow & 7;
        }
        uint2 p = pack_half4(x);
        const int chunk = k >> 6;
        const int byte = (k & 63) * 2;
        const int jlo = (f - 5 > 0) ? f - 5 : 0;
        const int jhi = (f < 2) ? f : 2;
        for (int j = jlo; j <= jhi; j++) {
            const int cr = v * 6 + f - j;
            char* base = (char*)(g_Ac + ((size_t)(j * 32 + chunk) * CMPAD + cr) * 64);
            *(uint2*)(base + (byte ^ ((cr & 7) << 4))) = p;
        }
    } else if (i < NQQ + NSQ + NWQ) {
        int ii = i - NQQ - NSQ;
        size_t e = (size_t)ii * 4;
        const int k = (int)(e & (DIM - 1));
        size_t r = e >> 11;
        const int n = (int)(r & (DOUT - 1));
        const int j = (int)(r >> 10);
        float4 x = *(const float4*)(W + (size_t)n * (3 * DIM) + (size_t)j * DIM + k);
        uint2 p = pack_half4(x);
        const int chunk = k >> 6;
        const int byte = (k & 63) * 2;
        char* base = (char*)(g_Wc + ((size_t)(j * 32 + chunk) * DOUT + n) * 64);
        *(uint2*)(base + (byte ^ ((n & 7) << 4))) = p;
    } else if (i < NQQ + NSQ + NWQ + NPQ) {
        int ii = i - NQQ - NSQ - NWQ;          // 16 chunks x 8 rows x 16 quads
        const int chunk = ii >> 7;
        const int rem = ii & 127;
        const int row = NWAY * SACT + (rem >> 4);
        const int byte = (rem & 15) * 8;
        char* base = (char*)(g_SEc + ((size_t)chunk * SPACK + row) * 64);
        *(uint2*)(base + (byte ^ ((row & 7) << 4))) = make_uint2(0, 0);
    }
}

// ---------------- stage 1: partial-embedding GEMM (bulk-fed) ----------------
__global__ __launch_bounds__(256, 2) void gemm1()
{
    extern __shared__ char smem[];
    __shared__ __align__(8) uint64_t mbarS[3];
    const int nBase = blockIdx.x * 128;
    const int j     = blockIdx.y;
    const int mBase = blockIdx.z * 128;

    float acc[4][4][4];
    #pragma unroll
    for (int a = 0; a < 4; a++)
        #pragma unroll
        for (int b = 0; b < 4; b++)
            #pragma unroll
            for (int c = 0; c < 4; c++) acc[a][b][c] = 0.f;

    mma_mainloop_bulk<32>(
        g_Ac + (size_t)j * 32 * CMPAD * 64, CMPAD, mBase,
        g_Wc + (size_t)j * 32 * DOUT * 64, DOUT, nBase,
        smem, mbarS, acc);

    // compact P row for (video v, slice j, r) = v*18 + j*6 + r
    const int tid = threadIdx.x, l = tid & 31;
    const int wm = (tid >> 5) >> 2, wn = (tid >> 5) & 3;
    #pragma unroll
    for (int mi = 0; mi < 4; mi++) {
        const int c0 = mBase + wm * 64 + mi * 16 + (l >> 2);
        const int o0 = (c0 / 6) * 18 + j * 6 + c0 % 6;
        const int c8 = c0 + 8;
        const int o8 = (c8 / 6) * 18 + j * 6 + c8 % 6;
        #pragma unroll
        for (int ni = 0; ni < 4; ni++) {
            const int col = nBase + wn * 32 + ni * 8 + (l & 3) * 2;
            *(__half2*)(g_P + (size_t)o0 * DOUT + col) =
                __floats2half2_rn(acc[mi][ni][0], acc[mi][ni][1]);
            *(__half2*)(g_P + (size_t)o8 * DOUT + col) =
                __floats2half2_rn(acc[mi][ni][2], acc[mi][ni][3]);
        }
    }
}

// ---------------- stage 2: fused per-video assembly (writes chunk-major) ---------
__device__ __forceinline__ void assemble_video(
    const __half* __restrict__ srcP,    // 18 rows x 1024 fp16 (contiguous)
    __half* __restrict__ dstPlane,      // chunk-major dest base (QEc or SEc)
    int planeRows, int rowBase,         // rows per chunk plane, first output row
    float* __restrict__ dstN,           // 56 norms
    const float* __restrict__ bias,
    char* smemRaw)
{
    __half* sP = (__half*)smemRaw;                       // 18*1024 fp16
    float* ws = (float*)(smemRaw + 18 * 1024 * 2);       // TN*8 floats
    const int tid = threadIdx.x;
    {
        const uint2* s = (const uint2*)srcP;
        uint2* d = (uint2*)sP;
        #pragma unroll
        for (int i = 0; i < 18; i++) d[i * 256 + tid] = s[i * 256 + tid];
    }
    __syncthreads();
    const int o = tid * 4;
    const float4 vb = *(const float4*)(bias + o);
    const int l = tid & 31, wid = tid >> 5;
    const int chunk = o >> 6;
    const int byte = (o & 63) * 2;
    #pragma unroll 4
    for (int t = 0; t < TN; t++) {
        const int r0i = TUP[t][0];          // j=0: r = f0
        const int r1i = 6 + TUP[t][1] - 1;  // j=1: r = f1-1
        const int r2i = 12 + TUP[t][2] - 2; // j=2: r = f2-2
        uint2 pa = *(const uint2*)(sP + r0i * DOUT + o);
        uint2 pb = *(const uint2*)(sP + r1i * DOUT + o);
        uint2 pc = *(const uint2*)(sP + r2i * DOUT + o);
        float2 a0 = __half22float2(*(__half2*)&pa.x), a1 = __half22float2(*(__half2*)&pa.y);
        float2 b0 = __half22float2(*(__half2*)&pb.x), b1 = __half22float2(*(__half2*)&pb.y);
        float2 c0 = __half22float2(*(__half2*)&pc.x), c1 = __half22float2(*(__half2*)&pc.y);
        float4 r;
        r.x = fmaxf(a0.x + b0.x + c0.x + vb.x, 0.f);
        r.y = fmaxf(a0.y + b0.y + c0.y + vb.y, 0.f);
        r.z = fmaxf(a1.x + b1.x + c1.x + vb.z, 0.f);
        r.w = fmaxf(a1.y + b1.y + c1.y + vb.w, 0.f);
        uint2 p = pack_half4(r);
        const int grow = rowBase + t;
        char* base = (char*)(dstPlane + ((size_t)chunk * planeRows + grow) * 64);
        *(uint2*)(base + (byte ^ ((grow & 7) << 4))) = p;
        float ss = sumsq_half4(p);
        #pragma unroll
        for (int s = 16; s > 0; s >>= 1) ss += __shfl_xor_sync(0xffffffffu, ss, s);
        if (l == 0) ws[t * 8 + wid] = ss;
    }
    __syncthreads();
    if (tid < TN) {
        float s = 0.f;
        #pragma unroll
        for (int i = 0; i < 8; i++) s += ws[tid * 8 + i];
        dstN[tid] = s;
    }
}

// grid: [0..NQ) queries | [NQ..NQ+NSUP) supports
__global__ __launch_bounds__(256) void assembleQS(const float* __restrict__ bias)
{
    extern __shared__ char sRaw[];
    const int b = blockIdx.x;
    if (b < NQ) {
        assemble_video(g_P + (size_t)b * 18 * DOUT,
                       g_QEc, QROWS, b * TN,
                       g_q2 + b * TN, bias, sRaw);
    } else {
        const int n = b - NQ;
        const int loc = g_sloc[n];                    // c*SHOT + shotRank
        const int base = (loc / SHOT) * SACT + (loc % SHOT) * TN;
        assemble_video(g_P + (size_t)(NQ + n) * 18 * DOUT,
                       g_SEc, SPACK, base,
                       g_s2 + base, bias, sRaw);
    }
}

// ---------------- stage 3: fused distance GEMM (bulk-fed) + class-half min -------
__global__ __launch_bounds__(256, 2) void gemm3()
{
    extern __shared__ char smem[];
    __shared__ __align__(8) uint64_t mbarS[3];
    __shared__ float s2s[128];
    __shared__ float rowmin[128][4][2];
    const int nt    = blockIdx.x;                // packed support tile
    const int nBase = nt * 128;
    const int mBase = blockIdx.y * 128;
    const int tid = threadIdx.x, l = tid & 31;
    const int wm = (tid >> 5) >> 2, wn = (tid >> 5) & 3;

    if (tid < 128) s2s[tid] = g_s2[nBase + tid];

    float acc[4][4][4];
    #pragma unroll
    for (int a = 0; a < 4; a++)
        #pragma unroll
        for (int b = 0; b < 4; b++)
            #pragma unroll
            for (int d = 0; d < 4; d++) acc[a][b][d] = 0.f;

    mma_mainloop_bulk<16>(
        g_QEc, QROWS, mBase,
        g_SEc, SPACK, nBase,
        smem, mbarS, acc);

    // segmented epilogue: tile spans at most 2 classes (boundary is even)
    const int cLo = min(nBase / SACT, NWAY - 1);
    float mnL0[4], mnL1[4], mnH0[4], mnH1[4];
    #pragma unroll
    for (int mi = 0; mi < 4; mi++) { mnL0[mi] = 3e38f; mnL1[mi] = 3e38f; mnH0[mi] = 3e38f; mnH1[mi] = 3e38f; }
    #pragma unroll
    for (int ni = 0; ni < 4; ni++) {
        const int col = wn * 32 + ni * 8 + (l & 3) * 2;
        const bool isHi = (min((nBase + col) / SACT, NWAY - 1) != cLo);
        const float sa = s2s[col], sbv = s2s[col + 1];
        #pragma unroll
        for (int mi = 0; mi < 4; mi++) {
            float v0 = fminf(fmaf(-2.f, acc[mi][ni][0], sa), fmaf(-2.f, acc[mi][ni][1], sbv));
            float v1 = fminf(fmaf(-2.f, acc[mi][ni][2], sa), fmaf(-2.f, acc[mi][ni][3], sbv));
            if (isHi) { mnH0[mi] = fminf(mnH0[mi], v0); mnH1[mi] = fminf(mnH1[mi], v1); }
            else      { mnL0[mi] = fminf(mnL0[mi], v0); mnL1[mi] = fminf(mnL1[mi], v1); }
        }
    }
    #pragma unroll
    for (int mi = 0; mi < 4; mi++) {
        #pragma unroll
        for (int s = 1; s <= 2; s <<= 1) {
            mnL0[mi] = fminf(mnL0[mi], __shfl_xor_sync(0xffffffffu, mnL0[mi], s));
            mnL1[mi] = fminf(mnL1[mi], __shfl_xor_sync(0xffffffffu, mnL1[mi], s));
            mnH0[mi] = fminf(mnH0[mi], __shfl_xor_sync(0xffffffffu, mnH0[mi], s));
            mnH1[mi] = fminf(mnH1[mi], __shfl_xor_sync(0xffffffffu, mnH1[mi], s));
        }
    }
    if ((l & 3) == 0) {
        #pragma unroll
        for (int mi = 0; mi < 4; mi++) {
            const int r0 = wm * 64 + mi * 16 + (l >> 2);
            rowmin[r0][wn][0] = mnL0[mi];      rowmin[r0][wn][1] = mnH0[mi];
            rowmin[r0 + 8][wn][0] = mnL1[mi];  rowmin[r0 + 8][wn][1] = mnH1[mi];
        }
    }
    __syncthreads();
    if (tid < 128) {
        float mL = fminf(fminf(rowmin[tid][0][0], rowmin[tid][1][0]),
                         fminf(rowmin[tid][2][0], rowmin[tid][3][0]));
        float mH = fminf(fminf(rowmin[tid][0][1], rowmin[tid][1][1]),
                         fminf(rowmin[tid][2][1], rowmin[tid][3][1]));
        g_tmin[2 * nt + 0][mBase + tid] = mL;
        g_tmin[2 * nt + 1][mBase + tid] = mH;
    }
}

// ---------------- stage 4: finalize ----------------
__global__ void finalize(float* __restrict__ out)
{
    int idx = blockIdx.x * blockDim.x + threadIdx.x;
    if (idx >= NQ * NWAY) return;
    int q = idx / NWAY, c = idx % NWAY;
    const int e0 = CLS_E[c][0], e1 = CLS_E[c][1], e2 = CLS_E[c][2];
    float s = 0.f;
    #pragma unroll 8
    for (int t = 0; t < TN; ++t) {
        const int row = q * TN + t;
        float m = fminf(fminf(g_tmin[e0][row], g_tmin[e1][row]), g_tmin[e2][row]);
        s += sqrtf(fmaxf(g_q2[row] + m, 0.f));
    }
    out[q * NWAY + c] = -s * (1.0f / (float)TN);
}

// ---------------- launch ----------------
extern "C" void kernel_launch(void* const* d_in, const int* in_sizes, int n_in,
                              void* d_out, int out_size)
{
    const float* support = (const float*)d_in[0];      // [25,8,2048]
    const int*   labraw  = (const int*)d_in[1];        // [25] int32/int64
    const float* queries = (const float*)d_in[2];      // [400,8,2048]
    const float* W       = (const float*)d_in[3];      // [1024,6144]
    const float* bias    = (const float*)d_in[4];      // [1024]
    float*       out     = (float*)d_out;              // [400,5]
    (void)in_sizes; (void)n_in; (void)out_size;

    cudaFuncSetAttribute(gemm1, cudaFuncAttributeMaxDynamicSharedMemorySize, SMEM_BYTES);
    cudaFuncSetAttribute(gemm3, cudaFuncAttributeMaxDynamicSharedMemorySize, SMEM_BYTES);
    cudaFuncSetAttribute(assembleQS, cudaFuncAttributeMaxDynamicSharedMemorySize, ASM_SMEM);

    convAll<<<(NQQ + NSQ + NWQ + NPQ + 255) / 256, 256>>>(queries, support, W, labraw);

    gemm1<<<dim3(DOUT / 128, 3, CMPAD / 128), 256, SMEM_BYTES>>>();

    assembleQS<<<NQ + NSUP, 256, ASM_SMEM>>>(bias);

    gemm3<<<dim3(NT3, NMT3), 256, SMEM_BYTES>>>();

    finalize<<<(NQ * NWAY + 255) / 256, 256>>>(out);
}